// round 14
// baseline (speedup 1.0000x reference)
#include <cuda_runtime.h>
#include <cuda_bf16.h>
#include <math.h>
#include <stdint.h>
#include <string.h>

#define VIEWS 1024
#define SS 64
#define DD 256
#define M_TOTAL (VIEWS * SS)   // 65536

// ---------------------------------------------------------------------------
// Scratch (allocation-free rule: __device__ globals). Activations as bf16 hi/lo.
// ---------------------------------------------------------------------------
__device__ __align__(256) __nv_bfloat16 g_qhi[(size_t)M_TOTAL * DD];
__device__ __align__(256) __nv_bfloat16 g_qlo[(size_t)M_TOTAL * DD];
__device__ __align__(256) __nv_bfloat16 g_khi[(size_t)M_TOTAL * DD];
__device__ __align__(256) __nv_bfloat16 g_klo[(size_t)M_TOTAL * DD];
__device__ __align__(256) __nv_bfloat16 g_vhi[(size_t)M_TOTAL * DD];
__device__ __align__(256) __nv_bfloat16 g_vlo[(size_t)M_TOTAL * DD];
__device__ __align__(256) __nv_bfloat16 g_aohi[(size_t)M_TOTAL * DD];
__device__ __align__(256) __nv_bfloat16 g_aolo[(size_t)M_TOTAL * DD];
__device__ float g_pe[SS * DD];
__device__ __align__(256) __nv_bfloat16 g_w_hi[4][DD * DD];
__device__ __align__(256) __nv_bfloat16 g_w_lo[4][DD * DD];

// ---------------------------------------------------------------------------
// PTX helpers
// ---------------------------------------------------------------------------
__device__ __forceinline__ uint32_t smem_to_u32(const void* p) {
    uint32_t a;
    asm("{ .reg .u64 t; cvta.to.shared.u64 t, %1; cvt.u32.u64 %0, t; }"
        : "=r"(a) : "l"(p));
    return a;
}
#define CP_ASYNC16(dst_u32, src_ptr) \
    asm volatile("cp.async.cg.shared.global [%0], [%1], 16;" \
        :: "r"(dst_u32), "l"(src_ptr))
#define CP_COMMIT() asm volatile("cp.async.commit_group;" ::: "memory")
#define CP_WAIT0()  asm volatile("cp.async.wait_group 0;" ::: "memory")
#define CP_WAIT1()  asm volatile("cp.async.wait_group 1;" ::: "memory")

__device__ __forceinline__ void ldsm4(uint32_t* r, uint32_t addr) {
    asm volatile("ldmatrix.sync.aligned.m8n8.x4.shared.b16 {%0,%1,%2,%3}, [%4];"
        : "=r"(r[0]), "=r"(r[1]), "=r"(r[2]), "=r"(r[3]) : "r"(addr));
}
__device__ __forceinline__ void ldsm4t(uint32_t* r, uint32_t addr) {
    asm volatile("ldmatrix.sync.aligned.m8n8.x4.trans.shared.b16 {%0,%1,%2,%3}, [%4];"
        : "=r"(r[0]), "=r"(r[1]), "=r"(r[2]), "=r"(r[3]) : "r"(addr));
}
__device__ __forceinline__ void mma16816(float* c, const uint32_t* a, const uint32_t* b) {
    asm volatile(
        "mma.sync.aligned.m16n8k16.row.col.f32.bf16.bf16.f32 "
        "{%0,%1,%2,%3}, {%4,%5,%6,%7}, {%8,%9}, {%0,%1,%2,%3};"
        : "+f"(c[0]), "+f"(c[1]), "+f"(c[2]), "+f"(c[3])
        : "r"(a[0]), "r"(a[1]), "r"(a[2]), "r"(a[3]), "r"(b[0]), "r"(b[1]));
}

__device__ __forceinline__ uint32_t pack2bf(float a, float b) {
    __nv_bfloat162 h = __floats2bfloat162_rn(a, b);
    uint32_t u; memcpy(&u, &h, 4); return u;
}
__device__ __forceinline__ void split2(float a, float b, uint32_t& hw, uint32_t& lw) {
    __nv_bfloat16 ha = __float2bfloat16_rn(a);
    __nv_bfloat16 hb = __float2bfloat16_rn(b);
    uint16_t ua, ub; memcpy(&ua, &ha, 2); memcpy(&ub, &hb, 2);
    hw = (uint32_t)ua | ((uint32_t)ub << 16);
    lw = pack2bf(a - __bfloat162float(ha), b - __bfloat162float(hb));
}

// ---------------------------------------------------------------------------
// Prep: posenc + all 4 weight splits in ONE launch
// ---------------------------------------------------------------------------
__global__ void prep_kernel(const float* __restrict__ Wq, const float* __restrict__ Wk,
                            const float* __restrict__ Wv, const float* __restrict__ Wo,
                            __nv_bfloat16* __restrict__ whi, __nv_bfloat16* __restrict__ wlo) {
    int b = blockIdx.x;
    int t = threadIdx.x;
    if (b < 64) {
        int idx = b * 256 + t;
        int s = idx / DD;
        int d = idx % DD;
        double angle = (double)s / pow(10000.0, (2.0 * (double)(d / 2)) / (double)DD);
        g_pe[idx] = (d & 1) ? (float)cos(angle) : (float)sin(angle);
    } else {
        int idx = (b - 64) * 256 + t;
        int w = idx >> 16;
        int i = idx & 65535;
        const float* W = (w == 0) ? Wq : (w == 1) ? Wk : (w == 2) ? Wv : Wo;
        float x = W[i];
        __nv_bfloat16 h = __float2bfloat16_rn(x);
        whi[(size_t)w * 65536 + i] = h;
        wlo[(size_t)w * 65536 + i] = __float2bfloat16_rn(x - __bfloat162float(h));
    }
}

// ---------------------------------------------------------------------------
// GEMM geometry: CTA tile 128x128, 256 thr, 8 warps (4m x 2n), warp tile 32x64.
// K = 8 chunks of 32. THREE cp.async stages of 32 KB (wait_group 1).
// Inner: frag reuse + TERM-MAJOR ordering (acc reuse distance 8).
// 96 KB smem/CTA + <=128 regs -> 2 CTAs/SM (192 KB <= 228 KB).
// ---------------------------------------------------------------------------
#define GSTAGE 32768
#define GSMEM_TOTAL (3 * GSTAGE)   // 98304
#define SWZ(r) (((r) >> 1) & 3)

#define TERM8(ACC, AF, BF, NH) \
    mma16816(ACC[0][(NH)*4 + 0], AF[0], &BF[0][0]); \
    mma16816(ACC[0][(NH)*4 + 1], AF[0], &BF[0][2]); \
    mma16816(ACC[0][(NH)*4 + 2], AF[0], &BF[1][0]); \
    mma16816(ACC[0][(NH)*4 + 3], AF[0], &BF[1][2]); \
    mma16816(ACC[1][(NH)*4 + 0], AF[1], &BF[0][0]); \
    mma16816(ACC[1][(NH)*4 + 1], AF[1], &BF[0][2]); \
    mma16816(ACC[1][(NH)*4 + 2], AF[1], &BF[1][0]); \
    mma16816(ACC[1][(NH)*4 + 3], AF[1], &BF[1][2]);

// ---- gemm_qkv FUSED over z=0,1,2 (q,k,v) ----
__global__ void __launch_bounds__(256, 2) gemm_qkv(
    const float* __restrict__ A0, const float* __restrict__ A1,
    const float* __restrict__ A2,
    const __nv_bfloat16* __restrict__ WhiB,
    const __nv_bfloat16* __restrict__ WloB,
    __nv_bfloat16* __restrict__ C0h, __nv_bfloat16* __restrict__ C0l,
    __nv_bfloat16* __restrict__ C1h, __nv_bfloat16* __restrict__ C1l,
    __nv_bfloat16* __restrict__ C2h, __nv_bfloat16* __restrict__ C2l)
{
    extern __shared__ char smem[];
    const uint32_t sbase = smem_to_u32(smem);
    const int t = threadIdx.x;
    const int wid = t >> 5, lane = t & 31;
    const int wm = wid >> 1, wn = wid & 1;
    const int m0 = blockIdx.x << 7;
    const int N0 = blockIdx.y << 7;
    const int z  = blockIdx.z;

    const float* A = (z == 0) ? A0 : (z == 1) ? A1 : A2;
    const __nv_bfloat16* Whi = WhiB + (size_t)z * 65536;
    const __nv_bfloat16* Wlo = WloB + (size_t)z * 65536;
    __nv_bfloat16* Chi = (z == 0) ? C0h : (z == 1) ? C1h : C2h;
    __nv_bfloat16* Clo = (z == 0) ? C0l : (z == 1) ? C1l : C2l;

    float accs[2][8][4];
    float* acc[2][8];
#pragma unroll
    for (int i = 0; i < 2; i++)
#pragma unroll
        for (int j = 0; j < 8; j++) {
            acc[i][j] = accs[i][j];
#pragma unroll
            for (int c = 0; c < 4; c++) accs[i][j][c] = 0.0f;
        }

    auto load_B = [&](int kc, int s) {
        const uint32_t bhi = sbase + s * GSTAGE + 16384;
        const uint32_t blo = bhi + 8192;
#pragma unroll
        for (int g = 0; g < 2; g++) {
            int idx = g * 256 + t;
            int nrow = idx >> 2;
            int u = idx & 3;
            size_t goff = (size_t)(N0 + nrow) * DD + kc * 32 + u * 8;
            uint32_t d = (uint32_t)(nrow * 64 + ((u ^ SWZ(nrow)) << 4));
            CP_ASYNC16(bhi + d, (const void*)(Whi + goff));
            CP_ASYNC16(blo + d, (const void*)(Wlo + goff));
        }
    };

    float4 areg[4];
    auto load_A = [&](int kc) {
#pragma unroll
        for (int g = 0; g < 4; g++) {
            int idx = g * 256 + t;
            int row = idx >> 3;
            int f4c = idx & 7;
            areg[g] = *(const float4*)(A + (size_t)(m0 + row) * DD + kc * 32 + f4c * 4);
        }
    };
    auto store_A = [&](int s) {
        char* ahi = smem + s * GSTAGE;
        char* alo = ahi + 8192;
#pragma unroll
        for (int g = 0; g < 4; g++) {
            int idx = g * 256 + t;
            int row = idx >> 3;
            int f4c = idx & 7;
            float4 v = areg[g];
            uint32_t h01, l01, h23, l23;
            split2(v.x, v.y, h01, l01);
            split2(v.z, v.w, h23, l23);
            uint64_t hi64 = (uint64_t)h01 | ((uint64_t)h23 << 32);
            uint64_t lo64 = (uint64_t)l01 | ((uint64_t)l23 << 32);
            int u = f4c >> 1, half = f4c & 1;
            int d = row * 64 + ((u ^ SWZ(row)) << 4) + half * 8;
            *(uint64_t*)(ahi + d) = hi64;
            *(uint64_t*)(alo + d) = lo64;
        }
    };

    // Prologue: B stages 0 and 1 in flight; A chunk 0 staged.
    load_B(0, 0);
    CP_COMMIT();
    load_B(1, 1);
    CP_COMMIT();
    load_A(0);
    store_A(0);

    const int q  = lane >> 3;
    const int r8 = lane & 7;
    int arow[2], brow[4];
#pragma unroll
    for (int mi = 0; mi < 2; mi++) arow[mi] = wm * 32 + mi * 16 + r8 + (q & 1) * 8;
#pragma unroll
    for (int ni = 0; ni < 4; ni++) brow[ni] = wn * 64 + ni * 16 + r8 + (q >> 1) * 8;
    const int a_kq = q >> 1;
    const int b_kq = q & 1;

    for (int kc = 0; kc < 8; kc++) {
        const int s = kc % 3;
        if (kc == 7) { CP_WAIT0(); } else { CP_WAIT1(); }
        __syncthreads();
        if (kc < 6) {
            load_B(kc + 2, (kc + 2) % 3);
            CP_COMMIT();
        }
        if (kc < 7) load_A(kc + 1);

        const uint32_t ah = sbase + s * GSTAGE;
        const uint32_t al = ah + 8192;
        const uint32_t bh = ah + 16384;
        const uint32_t bl = ah + 24576;
#pragma unroll
        for (int k16 = 0; k16 < 2; k16++) {
            uint32_t afh[2][4], afl[2][4];
#pragma unroll
            for (int mi = 0; mi < 2; mi++) {
                int ku = k16 * 2 + a_kq;
                uint32_t off = arow[mi] * 64 + ((ku ^ SWZ(arow[mi])) << 4);
                ldsm4(afh[mi], ah + off);
                ldsm4(afl[mi], al + off);
            }
#pragma unroll
            for (int nh = 0; nh < 2; nh++) {
                uint32_t bfh[2][4], bfl[2][4];
#pragma unroll
                for (int nj = 0; nj < 2; nj++) {
                    int ni = nh * 2 + nj;
                    int ku = k16 * 2 + b_kq;
                    uint32_t off = brow[ni] * 64 + ((ku ^ SWZ(brow[ni])) << 4);
                    ldsm4(bfh[nj], bh + off);
                    ldsm4(bfl[nj], bl + off);
                }
                TERM8(acc, afh, bfh, nh)
                TERM8(acc, afh, bfl, nh)
                TERM8(acc, afl, bfh, nh)
            }
        }
        if (kc < 7) store_A((kc + 1) % 3);
    }

    const int fr = lane >> 2;
    const int fc = (lane & 3) * 2;
#pragma unroll
    for (int mi = 0; mi < 2; mi++) {
#pragma unroll
        for (int half = 0; half < 2; half++) {
            const int mrow = m0 + wm * 32 + mi * 16 + fr + half * 8;
            const int sr = mrow & (SS - 1);
#pragma unroll
            for (int n8 = 0; n8 < 8; n8++) {
                const int ncol = N0 + wn * 64 + n8 * 8 + fc;
                float2 pe = *(const float2*)&g_pe[sr * DD + ncol];
                float v0 = accs[mi][n8][half * 2 + 0] + pe.x;
                float v1 = accs[mi][n8][half * 2 + 1] + pe.y;
                uint32_t hw, lw;
                split2(v0, v1, hw, lw);
                *(uint32_t*)&Chi[(size_t)mrow * DD + ncol] = hw;
                *(uint32_t*)&Clo[(size_t)mrow * DD + ncol] = lw;
            }
        }
    }
}

// ---- gemm_out: A+B via 3-stage cp.async; fp32 out with gelu+resid ----
__global__ void __launch_bounds__(256, 2) gemm_out(
    const __nv_bfloat16* __restrict__ Ahi,
    const __nv_bfloat16* __restrict__ Alo,
    const __nv_bfloat16* __restrict__ Whi,
    const __nv_bfloat16* __restrict__ Wlo,
    float* __restrict__ C,
    const float* __restrict__ bias,
    const float* __restrict__ resid)
{
    extern __shared__ char smem[];
    const uint32_t sbase = smem_to_u32(smem);
    const int t = threadIdx.x;
    const int wid = t >> 5, lane = t & 31;
    const int wm = wid >> 1, wn = wid & 1;
    const int m0 = blockIdx.x << 7;
    const int N0 = blockIdx.y << 7;

    float accs[2][8][4];
    float* acc[2][8];
#pragma unroll
    for (int i = 0; i < 2; i++)
#pragma unroll
        for (int j = 0; j < 8; j++) {
            acc[i][j] = accs[i][j];
#pragma unroll
            for (int c = 0; c < 4; c++) accs[i][j][c] = 0.0f;
        }

    auto load_AB = [&](int kc, int s) {
        const uint32_t ahi = sbase + s * GSTAGE;
        const uint32_t alo = ahi + 8192;
        const uint32_t bhi = ahi + 16384;
        const uint32_t blo = ahi + 24576;
#pragma unroll
        for (int g = 0; g < 2; g++) {
            int idx = g * 256 + t;
            int row = idx >> 2;
            int u = idx & 3;
            uint32_t d = (uint32_t)(row * 64 + ((u ^ SWZ(row)) << 4));
            size_t goffa = (size_t)(m0 + row) * DD + kc * 32 + u * 8;
            CP_ASYNC16(ahi + d, (const void*)(Ahi + goffa));
            CP_ASYNC16(alo + d, (const void*)(Alo + goffa));
            size_t goffb = (size_t)(N0 + row) * DD + kc * 32 + u * 8;
            CP_ASYNC16(bhi + d, (const void*)(Whi + goffb));
            CP_ASYNC16(blo + d, (const void*)(Wlo + goffb));
        }
    };

    load_AB(0, 0);
    CP_COMMIT();
    load_AB(1, 1);
    CP_COMMIT();

    const int q  = lane >> 3;
    const int r8 = lane & 7;
    int arow[2], brow[4];
#pragma unroll
    for (int mi = 0; mi < 2; mi++) arow[mi] = wm * 32 + mi * 16 + r8 + (q & 1) * 8;
#pragma unroll
    for (int ni = 0; ni < 4; ni++) brow[ni] = wn * 64 + ni * 16 + r8 + (q >> 1) * 8;
    const int a_kq = q >> 1;
    const int b_kq = q & 1;

    for (int kc = 0; kc < 8; kc++) {
        const int s = kc % 3;
        if (kc == 7) { CP_WAIT0(); } else { CP_WAIT1(); }
        __syncthreads();
        if (kc < 6) {
            load_AB(kc + 2, (kc + 2) % 3);
            CP_COMMIT();
        }
        const uint32_t ah = sbase + s * GSTAGE;
        const uint32_t al = ah + 8192;
        const uint32_t bh = ah + 16384;
        const uint32_t bl = ah + 24576;
#pragma unroll
        for (int k16 = 0; k16 < 2; k16++) {
            uint32_t afh[2][4], afl[2][4];
#pragma unroll
            for (int mi = 0; mi < 2; mi++) {
                int ku = k16 * 2 + a_kq;
                uint32_t off = arow[mi] * 64 + ((ku ^ SWZ(arow[mi])) << 4);
                ldsm4(afh[mi], ah + off);
                ldsm4(afl[mi], al + off);
            }
#pragma unroll
            for (int nh = 0; nh < 2; nh++) {
                uint32_t bfh[2][4], bfl[2][4];
#pragma unroll
                for (int nj = 0; nj < 2; nj++) {
                    int ni = nh * 2 + nj;
                    int ku = k16 * 2 + b_kq;
                    uint32_t off = brow[ni] * 64 + ((ku ^ SWZ(brow[ni])) << 4);
                    ldsm4(bfh[nj], bh + off);
                    ldsm4(bfl[nj], bl + off);
                }
                TERM8(acc, afh, bfh, nh)
                TERM8(acc, afh, bfl, nh)
                TERM8(acc, afl, bfh, nh)
            }
        }
    }

    const int fr = lane >> 2;
    const int fc = (lane & 3) * 2;
#pragma unroll
    for (int mi = 0; mi < 2; mi++) {
#pragma unroll
        for (int half = 0; half < 2; half++) {
            const int mrow = m0 + wm * 32 + mi * 16 + fr + half * 8;
#pragma unroll
            for (int n8 = 0; n8 < 8; n8++) {
                const int ncol = N0 + wn * 64 + n8 * 8 + fc;
                float2 bb = *(const float2*)&bias[ncol];
                float2 rr = *(const float2*)&resid[(size_t)mrow * DD + ncol];
                float x0 = accs[mi][n8][half * 2 + 0] + bb.x;
                float x1 = accs[mi][n8][half * 2 + 1] + bb.y;
                float v0 = 0.5f * x0 * (1.0f + erff(x0 * 0.70710678118654752f)) + rr.x;
                float v1 = 0.5f * x1 * (1.0f + erff(x1 * 0.70710678118654752f)) + rr.y;
                *(float2*)&C[(size_t)mrow * DD + ncol] = make_float2(v0, v1);
            }
        }
    }
}

// ---------------------------------------------------------------------------
// HMMA attention, 512 threads (16 warps); QK / V split-commit loads.
// ---------------------------------------------------------------------------
#define ASM_Q_HI 0
#define ASM_Q_LO 32768
#define ASM_K_HI 65536
#define ASM_K_LO 98304
#define ASM_V_HI 131072
#define ASM_V_LO 163840
#define ASM_STAT 196608
#define ASM_SPART 197632
#define ASM_P_HI 0
#define ASM_P_LO 8192
#define ATTN_SMEM (197632 + 64 * 68 * 4)   // 215040

__global__ void __launch_bounds__(512, 1) attn_hmma(
    const __nv_bfloat16* __restrict__ Qhi, const __nv_bfloat16* __restrict__ Qlo,
    const __nv_bfloat16* __restrict__ Khi, const __nv_bfloat16* __restrict__ Klo,
    const __nv_bfloat16* __restrict__ Vhi, const __nv_bfloat16* __restrict__ Vlo,
    __nv_bfloat16* __restrict__ Ohi, __nv_bfloat16* __restrict__ Olo)
{
    extern __shared__ char smem[];
    const uint32_t sbase = smem_to_u32(smem);
    const int t = threadIdx.x;
    const int wid = t >> 5, lane = t & 31;
    const int wk = wid >> 3;
    const int wid7 = wid & 7;
    const int wm = wid7 >> 1, wn = wid7 & 1;
    const int q  = lane >> 3, r8 = lane & 7;
    const size_t base = (size_t)blockIdx.x * SS * DD;

    // ---- Group 1: Q,K hi/lo. Group 2: V hi/lo (completes during S-phase). ----
    {
        const __nv_bfloat16* srcs[4] = { Qhi + base, Qlo + base, Khi + base, Klo + base };
        const int dsts[4] = { ASM_Q_HI, ASM_Q_LO, ASM_K_HI, ASM_K_LO };
#pragma unroll
        for (int a = 0; a < 4; a++) {
            const uint32_t dbase = sbase + dsts[a];
            const __nv_bfloat16* src = srcs[a];
#pragma unroll
            for (int g = 0; g < 4; g++) {
                int idx = g * 512 + t;
                int row = idx >> 5;
                int u = idx & 31;
                uint32_t d = row * 512 + ((u ^ (row & 7)) << 4);
                CP_ASYNC16(dbase + d, (const void*)(src + row * DD + u * 8));
            }
        }
    }
    CP_COMMIT();
    {
        const __nv_bfloat16* srcs[2] = { Vhi + base, Vlo + base };
        const int dsts[2] = { ASM_V_HI, ASM_V_LO };
#pragma unroll
        for (int a = 0; a < 2; a++) {
            const uint32_t dbase = sbase + dsts[a];
            const __nv_bfloat16* src = srcs[a];
#pragma unroll
            for (int g = 0; g < 4; g++) {
                int idx = g * 512 + t;
                int row = idx >> 5;
                int u = idx & 31;
                uint32_t d = row * 512 + ((u ^ (row & 7)) << 4);
                CP_ASYNC16(dbase + d, (const void*)(src + row * DD + u * 8));
            }
        }
    }
    CP_COMMIT();
    CP_WAIT1();            // Q,K resident; V still in flight
    __syncthreads();

    // ---- S-phase: each group covers k16 wk*8 .. wk*8+7 ----
    const int arow = wm * 16 + r8 + (q & 1) * 8;
    const int a_ku = q >> 1;
    int brow[2];
#pragma unroll
    for (int ni = 0; ni < 2; ni++) brow[ni] = wn * 32 + ni * 16 + r8 + (q >> 1) * 8;
    const int b_ku = q & 1;

    float sacc[4][4];
#pragma unroll
    for (int i = 0; i < 4; i++)
#pragma unroll
        for (int c = 0; c < 4; c++) sacc[i][c] = 0.0f;

    const uint32_t qhb = sbase + ASM_Q_HI, qlb = sbase + ASM_Q_LO;
    const uint32_t khb = sbase + ASM_K_HI, klb = sbase + ASM_K_LO;
#pragma unroll
    for (int kq16 = 0; kq16 < 8; kq16++) {
        const int ku = (wk * 8 + kq16) * 2;
        uint32_t afh[4], afl[4], bfh[2][4], bfl[2][4];
        uint32_t aoff = arow * 512 + (((ku + a_ku) ^ (arow & 7)) << 4);
        ldsm4(afh, qhb + aoff);
        ldsm4(afl, qlb + aoff);
#pragma unroll
        for (int ni = 0; ni < 2; ni++) {
            uint32_t boff = brow[ni] * 512 + (((ku + b_ku) ^ (brow[ni] & 7)) << 4);
            ldsm4(bfh[ni], khb + boff);
            ldsm4(bfl[ni], klb + boff);
        }
        mma16816(sacc[0], afh, &bfh[0][0]);
        mma16816(sacc[1], afh, &bfh[0][2]);
        mma16816(sacc[2], afh, &bfh[1][0]);
        mma16816(sacc[3], afh, &bfh[1][2]);
        mma16816(sacc[0], afh, &bfl[0][0]);
        mma16816(sacc[1], afh, &bfl[0][2]);
        mma16816(sacc[2], afh, &bfl[1][0]);
        mma16816(sacc[3], afh, &bfl[1][2]);
        mma16816(sacc[0], afl, &bfh[0][0]);
        mma16816(sacc[1], afl, &bfh[0][2]);
        mma16816(sacc[2], afl, &bfh[1][0]);
        mma16816(sacc[3], afl, &bfh[1][2]);
    }

    const int fr = lane >> 2;
    const int fc = (lane & 3) * 2;
    const int row0 = wm * 16 + fr;
    const int row1 = row0 + 8;

    // ---- reduce group-1 partial into group 0 ----
    float* Sp = (float*)(smem + ASM_SPART);   // [64][68]
    if (wk == 1) {
#pragma unroll
        for (int n8 = 0; n8 < 4; n8++) {
            const int col = wn * 32 + n8 * 8 + fc;
            Sp[row0 * 68 + col]     = sacc[n8][0];
            Sp[row0 * 68 + col + 1] = sacc[n8][1];
            Sp[row1 * 68 + col]     = sacc[n8][2];
            Sp[row1 * 68 + col + 1] = sacc[n8][3];
        }
    }
    __syncthreads();
    if (wk == 0) {
#pragma unroll
        for (int n8 = 0; n8 < 4; n8++) {
            const int col = wn * 32 + n8 * 8 + fc;
            sacc[n8][0] += Sp[row0 * 68 + col];
            sacc[n8][1] += Sp[row0 * 68 + col + 1];
            sacc[n8][2] += Sp[row1 * 68 + col];
            sacc[n8][3] += Sp[row1 * 68 + col + 1];
        }
    }

    // ---- Softmax (group 0 holds full S; all threads run, writes guarded) ----
    float* stat = (float*)(smem + ASM_STAT);

#pragma unroll
    for (int n8 = 0; n8 < 4; n8++)
#pragma unroll
        for (int c = 0; c < 4; c++) sacc[n8][c] *= 0.0625f;

    float m0 = -1e30f, m1 = -1e30f;
#pragma unroll
    for (int n8 = 0; n8 < 4; n8++) {
        m0 = fmaxf(m0, fmaxf(sacc[n8][0], sacc[n8][1]));
        m1 = fmaxf(m1, fmaxf(sacc[n8][2], sacc[n8][3]));
    }
    m0 = fmaxf(m0, __shfl_xor_sync(0xffffffffu, m0, 1));
    m0 = fmaxf(m0, __shfl_xor_sync(0xffffffffu, m0, 2));
    m1 = fmaxf(m1, __shfl_xor_sync(0xffffffffu, m1, 1));
    m1 = fmaxf(m1, __shfl_xor_sync(0xffffffffu, m1, 2));
    if (wk == 0 && (lane & 3) == 0) {
        stat[row0 * 2 + wn] = m0;
        stat[row1 * 2 + wn] = m1;
    }
    __syncthreads();
    m0 = fmaxf(stat[row0 * 2], stat[row0 * 2 + 1]);
    m1 = fmaxf(stat[row1 * 2], stat[row1 * 2 + 1]);

    float s0 = 0.0f, s1 = 0.0f;
#pragma unroll
    for (int n8 = 0; n8 < 4; n8++) {
        float p0 = expf(sacc[n8][0] - m0); sacc[n8][0] = p0;
        float p1 = expf(sacc[n8][1] - m0); sacc[n8][1] = p1;
        float p2 = expf(sacc[n8][2] - m1); sacc[n8][2] = p2;
        float p3 = expf(sacc[n8][3] - m1); sacc[n8][3] = p3;
        s0 += p0 + p1; s1 += p2 + p3;
    }
    s0 += __shfl_xor_sync(0xffffffffu, s0, 1);
    s0 += __shfl_xor_sync(0xffffffffu, s0, 2);
    s1 += __shfl_xor_sync(0xffffffffu, s1, 1);
    s1 += __shfl_xor_sync(0xffffffffu, s1, 2);
    if (wk == 0 && (lane & 3) == 0) {
        stat[128 + row0 * 2 + wn] = s0;
        stat[128 + row1 * 2 + wn] = s1;
    }
    __syncthreads();
    const float inv0 = 1.0f / (stat[128 + row0 * 2] + stat[128 + row0 * 2 + 1]);
    const float inv1 = 1.0f / (stat[128 + row1 * 2] + stat[128 + row1 * 2 + 1]);

    // ---- Write P (hi/lo split) into smem over dead Q area (group 0 only) ----
    if (wk == 0) {
        char* phi = smem + ASM_P_HI;
        char* plo = smem + ASM_P_LO;
#pragma unroll
        for (int n8 = 0; n8 < 4; n8++) {
            const int j = wn * 32 + n8 * 8 + fc;
            const int u = j >> 3, b = (j & 7) * 2;
            float p0 = sacc[n8][0] * inv0, p1 = sacc[n8][1] * inv0;
            uint32_t hw, lw;
            split2(p0, p1, hw, lw);
            int off0 = row0 * 128 + ((u ^ (row0 & 7)) << 4) + b;
            *(uint32_t*)(phi + off0) = hw;
            *(uint32_t*)(plo + off0) = lw;
            float p2 = sacc[n8][2] * inv1, p3 = sacc[n8][3] * inv1;
            split2(p2, p3, hw, lw);
            int off1 = row1 * 128 + ((u ^ (row1 & 7)) << 4) + b;
            *(uint32_t*)(phi + off1) = hw;
            *(uint32_t*)(plo + off1) = lw;
        }
    }
    CP_WAIT0();            // V resident before P@V
    __syncthreads();

    // ---- P@V: 16 warps as 4m x 4d, warp tile 16(m) x 64(d) ----
    const int wm2 = wid >> 2;
    const int wd  = wid & 3;
    float oacc[8][4];
#pragma unroll
    for (int i = 0; i < 8; i++)
#pragma unroll
        for (int c = 0; c < 4; c++) oacc[i][c] = 0.0f;

    const uint32_t phb = sbase + ASM_P_HI;
    const uint32_t plb = sbase + ASM_P_LO;
    const uint32_t vhb = sbase + ASM_V_HI;
    const uint32_t vlb = sbase + ASM_V_LO;
    const int arow2 = wm2 * 16 + r8 + (q & 1) * 8;

#pragma unroll
    for (int k16 = 0; k16 < 4; k16++) {
        uint32_t ph[4], pl[4];
        uint32_t aoff = arow2 * 128 + (((k16 * 2 + a_ku) ^ (arow2 & 7)) << 4);
        ldsm4(ph, phb + aoff);
        ldsm4(pl, plb + aoff);
        const int jrow = k16 * 16 + (q & 1) * 8 + r8;
#pragma unroll
        for (int dp = 0; dp < 2; dp++) {
            uint32_t vh0[4], vl0[4], vh1[4], vl1[4];
            const int u0 = wd * 8 + (dp * 2) * 2 + (q >> 1);
            const int u1 = wd * 8 + (dp * 2 + 1) * 2 + (q >> 1);
            uint32_t voff0 = jrow * 512 + ((u0 ^ (jrow & 7)) << 4);
            uint32_t voff1 = jrow * 512 + ((u1 ^ (jrow & 7)) << 4);
            ldsm4t(vh0, vhb + voff0);
            ldsm4t(vl0, vlb + voff0);
            ldsm4t(vh1, vhb + voff1);
            ldsm4t(vl1, vlb + voff1);
            float* o0 = oacc[dp * 4 + 0];
            float* o1 = oacc[dp * 4 + 1];
            float* o2 = oacc[dp * 4 + 2];
            float* o3 = oacc[dp * 4 + 3];
            mma16816(o0, ph, &vh0[0]);  mma16816(o1, ph, &vh0[2]);
            mma16816(o2, ph, &vh1[0]);  mma16816(o3, ph, &vh1[2]);
            mma16816(o0, ph, &vl0[0]);  mma16816(o1, ph, &vl0[2]);
            mma16816(o2, ph, &vl1[0]);  mma16816(o3, ph, &vl1[2]);
            mma16816(o0, pl, &vh0[0]);  mma16816(o1, pl, &vh0[2]);
            mma16816(o2, pl, &vh1[0]);  mma16816(o3, pl, &vh1[2]);
        }
    }

    // ---- Output: bf16 hi/lo 4B stores from fragments ----
    const int prow0 = wm2 * 16 + fr;
    const int prow1 = prow0 + 8;
#pragma unroll
    for (int n8 = 0; n8 < 8; n8++) {
        const int d = wd * 64 + n8 * 8 + fc;
        uint32_t hw, lw;
        split2(oacc[n8][0], oacc[n8][1], hw, lw);
        *(uint32_t*)&Ohi[base + (size_t)prow0 * DD + d] = hw;
        *(uint32_t*)&Olo[base + (size_t)prow0 * DD + d] = lw;
        split2(oacc[n8][2], oacc[n8][3], hw, lw);
        *(uint32_t*)&Ohi[base + (size_t)prow1 * DD + d] = hw;
        *(uint32_t*)&Olo[base + (size_t)prow1 * DD + d] = lw;
    }
}

// ---------------------------------------------------------------------------
extern "C" void kernel_launch(void* const* d_in, const int* in_sizes, int n_in,
                              void* d_out, int out_size) {
    (void)in_sizes; (void)n_in; (void)out_size;
    const float* q  = (const float*)d_in[0];
    const float* k  = (const float*)d_in[1];
    const float* v  = (const float*)d_in[2];
    const float* Wq = (const float*)d_in[3];
    const float* Wk = (const float*)d_in[4];
    const float* Wv = (const float*)d_in[5];
    const float* Wo = (const float*)d_in[6];
    const float* bo = (const float*)d_in[7];
    float* out = (float*)d_out;

    __nv_bfloat16 *qhi, *qlo, *khi, *klo, *vhi, *vlo, *aohi, *aolo, *whi, *wlo;
    cudaGetSymbolAddress((void**)&qhi, g_qhi);
    cudaGetSymbolAddress((void**)&qlo, g_qlo);
    cudaGetSymbolAddress((void**)&khi, g_khi);
    cudaGetSymbolAddress((void**)&klo, g_klo);
    cudaGetSymbolAddress((void**)&vhi, g_vhi);
    cudaGetSymbolAddress((void**)&vlo, g_vlo);
    cudaGetSymbolAddress((void**)&aohi, g_aohi);
    cudaGetSymbolAddress((void**)&aolo, g_aolo);
    cudaGetSymbolAddress((void**)&whi, g_w_hi);
    cudaGetSymbolAddress((void**)&wlo, g_w_lo);

    prep_kernel<<<64 + 1024, 256>>>(Wq, Wk, Wv, Wo, whi, wlo);

    cudaFuncSetAttribute(gemm_qkv, cudaFuncAttributeMaxDynamicSharedMemorySize, GSMEM_TOTAL);
    cudaFuncSetAttribute(gemm_out, cudaFuncAttributeMaxDynamicSharedMemorySize, GSMEM_TOTAL);
    cudaFuncSetAttribute(attn_hmma, cudaFuncAttributeMaxDynamicSharedMemorySize, ATTN_SMEM);

    dim3 gg(M_TOTAL / 128, 2, 3);
    gemm_qkv<<<gg, 256, GSMEM_TOTAL>>>(q, k, v, whi, wlo,
                                       qhi, qlo, khi, klo, vhi, vlo);

    attn_hmma<<<VIEWS, 512, ATTN_SMEM>>>(qhi, qlo, khi, klo, vhi, vlo, aohi, aolo);

    dim3 go(M_TOTAL / 128, 2);
    gemm_out<<<go, 256, GSMEM_TOTAL>>>(aohi, aolo, whi + 3 * DD * DD, wlo + 3 * DD * DD,
                                       out, bo, q);
}

// round 15
// speedup vs baseline: 1.0047x; 1.0047x over previous
#include <cuda_runtime.h>
#include <cuda_bf16.h>
#include <math.h>
#include <stdint.h>
#include <string.h>

#define VIEWS 1024
#define SS 64
#define DD 256
#define M_TOTAL (VIEWS * SS)   // 65536

// ---------------------------------------------------------------------------
// Scratch (allocation-free rule: __device__ globals). Activations as bf16 hi/lo.
// ---------------------------------------------------------------------------
__device__ __align__(256) __nv_bfloat16 g_qhi[(size_t)M_TOTAL * DD];
__device__ __align__(256) __nv_bfloat16 g_qlo[(size_t)M_TOTAL * DD];
__device__ __align__(256) __nv_bfloat16 g_khi[(size_t)M_TOTAL * DD];
__device__ __align__(256) __nv_bfloat16 g_klo[(size_t)M_TOTAL * DD];
__device__ __align__(256) __nv_bfloat16 g_vhi[(size_t)M_TOTAL * DD];
__device__ __align__(256) __nv_bfloat16 g_vlo[(size_t)M_TOTAL * DD];
__device__ __align__(256) __nv_bfloat16 g_aohi[(size_t)M_TOTAL * DD];
__device__ __align__(256) __nv_bfloat16 g_aolo[(size_t)M_TOTAL * DD];
__device__ float g_pe[SS * DD];
__device__ __align__(256) __nv_bfloat16 g_w_hi[4][DD * DD];
__device__ __align__(256) __nv_bfloat16 g_w_lo[4][DD * DD];

// ---------------------------------------------------------------------------
// PTX helpers
// ---------------------------------------------------------------------------
__device__ __forceinline__ uint32_t smem_to_u32(const void* p) {
    uint32_t a;
    asm("{ .reg .u64 t; cvta.to.shared.u64 t, %1; cvt.u32.u64 %0, t; }"
        : "=r"(a) : "l"(p));
    return a;
}
#define CP_ASYNC16(dst_u32, src_ptr) \
    asm volatile("cp.async.cg.shared.global [%0], [%1], 16;" \
        :: "r"(dst_u32), "l"(src_ptr))
#define CP_COMMIT() asm volatile("cp.async.commit_group;" ::: "memory")
#define CP_WAIT0()  asm volatile("cp.async.wait_group 0;" ::: "memory")

__device__ __forceinline__ void ldsm4(uint32_t* r, uint32_t addr) {
    asm volatile("ldmatrix.sync.aligned.m8n8.x4.shared.b16 {%0,%1,%2,%3}, [%4];"
        : "=r"(r[0]), "=r"(r[1]), "=r"(r[2]), "=r"(r[3]) : "r"(addr));
}
__device__ __forceinline__ void ldsm4t(uint32_t* r, uint32_t addr) {
    asm volatile("ldmatrix.sync.aligned.m8n8.x4.trans.shared.b16 {%0,%1,%2,%3}, [%4];"
        : "=r"(r[0]), "=r"(r[1]), "=r"(r[2]), "=r"(r[3]) : "r"(addr));
}
__device__ __forceinline__ void mma16816(float* c, const uint32_t* a, const uint32_t* b) {
    asm volatile(
        "mma.sync.aligned.m16n8k16.row.col.f32.bf16.bf16.f32 "
        "{%0,%1,%2,%3}, {%4,%5,%6,%7}, {%8,%9}, {%0,%1,%2,%3};"
        : "+f"(c[0]), "+f"(c[1]), "+f"(c[2]), "+f"(c[3])
        : "r"(a[0]), "r"(a[1]), "r"(a[2]), "r"(a[3]), "r"(b[0]), "r"(b[1]));
}

__device__ __forceinline__ uint32_t pack2bf(float a, float b) {
    __nv_bfloat162 h = __floats2bfloat162_rn(a, b);
    uint32_t u; memcpy(&u, &h, 4); return u;
}
__device__ __forceinline__ void split2(float a, float b, uint32_t& hw, uint32_t& lw) {
    __nv_bfloat16 ha = __float2bfloat16_rn(a);
    __nv_bfloat16 hb = __float2bfloat16_rn(b);
    uint16_t ua, ub; memcpy(&ua, &ha, 2); memcpy(&ub, &hb, 2);
    hw = (uint32_t)ua | ((uint32_t)ub << 16);
    lw = pack2bf(a - __bfloat162float(ha), b - __bfloat162float(hb));
}

// ---------------------------------------------------------------------------
// Prep: posenc + all 4 weight splits in ONE launch
// ---------------------------------------------------------------------------
__global__ void prep_kernel(const float* __restrict__ Wq, const float* __restrict__ Wk,
                            const float* __restrict__ Wv, const float* __restrict__ Wo,
                            __nv_bfloat16* __restrict__ whi, __nv_bfloat16* __restrict__ wlo) {
    int b = blockIdx.x;
    int t = threadIdx.x;
    if (b < 64) {
        int idx = b * 256 + t;
        int s = idx / DD;
        int d = idx % DD;
        double angle = (double)s / pow(10000.0, (2.0 * (double)(d / 2)) / (double)DD);
        g_pe[idx] = (d & 1) ? (float)cos(angle) : (float)sin(angle);
    } else {
        int idx = (b - 64) * 256 + t;
        int w = idx >> 16;
        int i = idx & 65535;
        const float* W = (w == 0) ? Wq : (w == 1) ? Wk : (w == 2) ? Wv : Wo;
        float x = W[i];
        __nv_bfloat16 h = __float2bfloat16_rn(x);
        whi[(size_t)w * 65536 + i] = h;
        wlo[(size_t)w * 65536 + i] = __float2bfloat16_rn(x - __bfloat162float(h));
    }
}

// ---------------------------------------------------------------------------
// GEMM geometry (R13 structure): CTA tile 128x128, 256 thr, 8 warps (4m x 2n),
// warp tile 32x64. K = 8 chunks of 32, TWO stages of 32 KB.
// Inner (NEW): load ALL A+B frags per k16 (12 LDSM), 3 terms over all 16
// accumulators -> acc reuse distance 16.
// ---------------------------------------------------------------------------
#define GSTAGE 32768
#define GSMEM_TOTAL (2 * GSTAGE)
#define SWZ(r) (((r) >> 1) & 3)

// One term = 16 MMAs over all 16 accumulators (distance 16).
// j: 0..7 -> ni = j>>1, half = j&1.
#define TERM16(ACC, AF, BFH_) \
    mma16816(ACC[0][0], AF[0], &BFH_[0][0]); \
    mma16816(ACC[0][1], AF[0], &BFH_[0][2]); \
    mma16816(ACC[0][2], AF[0], &BFH_[1][0]); \
    mma16816(ACC[0][3], AF[0], &BFH_[1][2]); \
    mma16816(ACC[0][4], AF[0], &BFH_[2][0]); \
    mma16816(ACC[0][5], AF[0], &BFH_[2][2]); \
    mma16816(ACC[0][6], AF[0], &BFH_[3][0]); \
    mma16816(ACC[0][7], AF[0], &BFH_[3][2]); \
    mma16816(ACC[1][0], AF[1], &BFH_[0][0]); \
    mma16816(ACC[1][1], AF[1], &BFH_[0][2]); \
    mma16816(ACC[1][2], AF[1], &BFH_[1][0]); \
    mma16816(ACC[1][3], AF[1], &BFH_[1][2]); \
    mma16816(ACC[1][4], AF[1], &BFH_[2][0]); \
    mma16816(ACC[1][5], AF[1], &BFH_[2][2]); \
    mma16816(ACC[1][6], AF[1], &BFH_[3][0]); \
    mma16816(ACC[1][7], AF[1], &BFH_[3][2]);

// ---- gemm_qkv FUSED over z=0,1,2 (q,k,v) ----
__global__ void __launch_bounds__(256, 2) gemm_qkv(
    const float* __restrict__ A0, const float* __restrict__ A1,
    const float* __restrict__ A2,
    const __nv_bfloat16* __restrict__ WhiB,
    const __nv_bfloat16* __restrict__ WloB,
    __nv_bfloat16* __restrict__ C0h, __nv_bfloat16* __restrict__ C0l,
    __nv_bfloat16* __restrict__ C1h, __nv_bfloat16* __restrict__ C1l,
    __nv_bfloat16* __restrict__ C2h, __nv_bfloat16* __restrict__ C2l)
{
    extern __shared__ char smem[];
    const uint32_t sbase = smem_to_u32(smem);
    const int t = threadIdx.x;
    const int wid = t >> 5, lane = t & 31;
    const int wm = wid >> 1, wn = wid & 1;
    const int m0 = blockIdx.x << 7;
    const int N0 = blockIdx.y << 7;
    const int z  = blockIdx.z;

    const float* A = (z == 0) ? A0 : (z == 1) ? A1 : A2;
    const __nv_bfloat16* Whi = WhiB + (size_t)z * 65536;
    const __nv_bfloat16* Wlo = WloB + (size_t)z * 65536;
    __nv_bfloat16* Chi = (z == 0) ? C0h : (z == 1) ? C1h : C2h;
    __nv_bfloat16* Clo = (z == 0) ? C0l : (z == 1) ? C1l : C2l;

    float accs[2][8][4];
    float* acc[2][8];
#pragma unroll
    for (int i = 0; i < 2; i++)
#pragma unroll
        for (int j = 0; j < 8; j++) {
            acc[i][j] = accs[i][j];
#pragma unroll
            for (int c = 0; c < 4; c++) accs[i][j][c] = 0.0f;
        }

    auto load_B = [&](int kc, int s) {
        const uint32_t bhi = sbase + s * GSTAGE + 16384;
        const uint32_t blo = bhi + 8192;
#pragma unroll
        for (int g = 0; g < 2; g++) {
            int idx = g * 256 + t;
            int nrow = idx >> 2;
            int u = idx & 3;
            size_t goff = (size_t)(N0 + nrow) * DD + kc * 32 + u * 8;
            uint32_t d = (uint32_t)(nrow * 64 + ((u ^ SWZ(nrow)) << 4));
            CP_ASYNC16(bhi + d, (const void*)(Whi + goff));
            CP_ASYNC16(blo + d, (const void*)(Wlo + goff));
        }
    };

    float4 areg[4];
    auto load_A = [&](int kc) {
#pragma unroll
        for (int g = 0; g < 4; g++) {
            int idx = g * 256 + t;
            int row = idx >> 3;
            int f4c = idx & 7;
            areg[g] = *(const float4*)(A + (size_t)(m0 + row) * DD + kc * 32 + f4c * 4);
        }
    };
    auto store_A = [&](int s) {
        char* ahi = smem + s * GSTAGE;
        char* alo = ahi + 8192;
#pragma unroll
        for (int g = 0; g < 4; g++) {
            int idx = g * 256 + t;
            int row = idx >> 3;
            int f4c = idx & 7;
            float4 v = areg[g];
            uint32_t h01, l01, h23, l23;
            split2(v.x, v.y, h01, l01);
            split2(v.z, v.w, h23, l23);
            uint64_t hi64 = (uint64_t)h01 | ((uint64_t)h23 << 32);
            uint64_t lo64 = (uint64_t)l01 | ((uint64_t)l23 << 32);
            int u = f4c >> 1, half = f4c & 1;
            int d = row * 64 + ((u ^ SWZ(row)) << 4) + half * 8;
            *(uint64_t*)(ahi + d) = hi64;
            *(uint64_t*)(alo + d) = lo64;
        }
    };

    load_B(0, 0);
    CP_COMMIT();
    load_A(0);
    store_A(0);

    const int q  = lane >> 3;
    const int r8 = lane & 7;
    int arow[2], brow[4];
#pragma unroll
    for (int mi = 0; mi < 2; mi++) arow[mi] = wm * 32 + mi * 16 + r8 + (q & 1) * 8;
#pragma unroll
    for (int ni = 0; ni < 4; ni++) brow[ni] = wn * 64 + ni * 16 + r8 + (q >> 1) * 8;
    const int a_kq = q >> 1;
    const int b_kq = q & 1;

    for (int kc = 0; kc < 8; kc++) {
        const int s = kc & 1;
        CP_WAIT0();
        __syncthreads();
        if (kc < 7) {
            load_B(kc + 1, s ^ 1);
            CP_COMMIT();
            load_A(kc + 1);
        }
        const uint32_t ah = sbase + s * GSTAGE;
        const uint32_t al = ah + 8192;
        const uint32_t bh = ah + 16384;
        const uint32_t bl = ah + 24576;
#pragma unroll
        for (int k16 = 0; k16 < 2; k16++) {
            uint32_t afh[2][4], afl[2][4], bfh[4][4], bfl[4][4];
#pragma unroll
            for (int mi = 0; mi < 2; mi++) {
                int ku = k16 * 2 + a_kq;
                uint32_t off = arow[mi] * 64 + ((ku ^ SWZ(arow[mi])) << 4);
                ldsm4(afh[mi], ah + off);
                ldsm4(afl[mi], al + off);
            }
#pragma unroll
            for (int ni = 0; ni < 4; ni++) {
                int ku = k16 * 2 + b_kq;
                uint32_t off = brow[ni] * 64 + ((ku ^ SWZ(brow[ni])) << 4);
                ldsm4(bfh[ni], bh + off);
                ldsm4(bfl[ni], bl + off);
            }
            TERM16(acc, afh, bfh)   // hi*hi
            TERM16(acc, afh, bfl)   // hi*lo
            TERM16(acc, afl, bfh)   // lo*hi
        }
        if (kc < 7) store_A(s ^ 1);
    }

    const int fr = lane >> 2;
    const int fc = (lane & 3) * 2;
#pragma unroll
    for (int mi = 0; mi < 2; mi++) {
#pragma unroll
        for (int half = 0; half < 2; half++) {
            const int mrow = m0 + wm * 32 + mi * 16 + fr + half * 8;
            const int sr = mrow & (SS - 1);
#pragma unroll
            for (int n8 = 0; n8 < 8; n8++) {
                const int ncol = N0 + wn * 64 + n8 * 8 + fc;
                float2 pe = *(const float2*)&g_pe[sr * DD + ncol];
                float v0 = accs[mi][n8][half * 2 + 0] + pe.x;
                float v1 = accs[mi][n8][half * 2 + 1] + pe.y;
                uint32_t hw, lw;
                split2(v0, v1, hw, lw);
                *(uint32_t*)&Chi[(size_t)mrow * DD + ncol] = hw;
                *(uint32_t*)&Clo[(size_t)mrow * DD + ncol] = lw;
            }
        }
    }
}

// ---- gemm_out: A pre-split bf16 via cp.async; fp32 out with gelu+resid ----
__global__ void __launch_bounds__(256, 2) gemm_out(
    const __nv_bfloat16* __restrict__ Ahi,
    const __nv_bfloat16* __restrict__ Alo,
    const __nv_bfloat16* __restrict__ Whi,
    const __nv_bfloat16* __restrict__ Wlo,
    float* __restrict__ C,
    const float* __restrict__ bias,
    const float* __restrict__ resid)
{
    extern __shared__ char smem[];
    const uint32_t sbase = smem_to_u32(smem);
    const int t = threadIdx.x;
    const int wid = t >> 5, lane = t & 31;
    const int wm = wid >> 1, wn = wid & 1;
    const int m0 = blockIdx.x << 7;
    const int N0 = blockIdx.y << 7;

    float accs[2][8][4];
    float* acc[2][8];
#pragma unroll
    for (int i = 0; i < 2; i++)
#pragma unroll
        for (int j = 0; j < 8; j++) {
            acc[i][j] = accs[i][j];
#pragma unroll
            for (int c = 0; c < 4; c++) accs[i][j][c] = 0.0f;
        }

    auto load_AB = [&](int kc, int s) {
        const uint32_t ahi = sbase + s * GSTAGE;
        const uint32_t alo = ahi + 8192;
        const uint32_t bhi = ahi + 16384;
        const uint32_t blo = ahi + 24576;
#pragma unroll
        for (int g = 0; g < 2; g++) {
            int idx = g * 256 + t;
            int row = idx >> 2;
            int u = idx & 3;
            uint32_t d = (uint32_t)(row * 64 + ((u ^ SWZ(row)) << 4));
            size_t goffa = (size_t)(m0 + row) * DD + kc * 32 + u * 8;
            CP_ASYNC16(ahi + d, (const void*)(Ahi + goffa));
            CP_ASYNC16(alo + d, (const void*)(Alo + goffa));
            size_t goffb = (size_t)(N0 + row) * DD + kc * 32 + u * 8;
            CP_ASYNC16(bhi + d, (const void*)(Whi + goffb));
            CP_ASYNC16(blo + d, (const void*)(Wlo + goffb));
        }
    };

    load_AB(0, 0);
    CP_COMMIT();

    const int q  = lane >> 3;
    const int r8 = lane & 7;
    int arow[2], brow[4];
#pragma unroll
    for (int mi = 0; mi < 2; mi++) arow[mi] = wm * 32 + mi * 16 + r8 + (q & 1) * 8;
#pragma unroll
    for (int ni = 0; ni < 4; ni++) brow[ni] = wn * 64 + ni * 16 + r8 + (q >> 1) * 8;
    const int a_kq = q >> 1;
    const int b_kq = q & 1;

    for (int kc = 0; kc < 8; kc++) {
        const int s = kc & 1;
        CP_WAIT0();
        __syncthreads();
        if (kc < 7) {
            load_AB(kc + 1, s ^ 1);
            CP_COMMIT();
        }
        const uint32_t ah = sbase + s * GSTAGE;
        const uint32_t al = ah + 8192;
        const uint32_t bh = ah + 16384;
        const uint32_t bl = ah + 24576;
#pragma unroll
        for (int k16 = 0; k16 < 2; k16++) {
            uint32_t afh[2][4], afl[2][4], bfh[4][4], bfl[4][4];
#pragma unroll
            for (int mi = 0; mi < 2; mi++) {
                int ku = k16 * 2 + a_kq;
                uint32_t off = arow[mi] * 64 + ((ku ^ SWZ(arow[mi])) << 4);
                ldsm4(afh[mi], ah + off);
                ldsm4(afl[mi], al + off);
            }
#pragma unroll
            for (int ni = 0; ni < 4; ni++) {
                int ku = k16 * 2 + b_kq;
                uint32_t off = brow[ni] * 64 + ((ku ^ SWZ(brow[ni])) << 4);
                ldsm4(bfh[ni], bh + off);
                ldsm4(bfl[ni], bl + off);
            }
            TERM16(acc, afh, bfh)
            TERM16(acc, afh, bfl)
            TERM16(acc, afl, bfh)
        }
    }

    const int fr = lane >> 2;
    const int fc = (lane & 3) * 2;
#pragma unroll
    for (int mi = 0; mi < 2; mi++) {
#pragma unroll
        for (int half = 0; half < 2; half++) {
            const int mrow = m0 + wm * 32 + mi * 16 + fr + half * 8;
#pragma unroll
            for (int n8 = 0; n8 < 8; n8++) {
                const int ncol = N0 + wn * 64 + n8 * 8 + fc;
                float2 bb = *(const float2*)&bias[ncol];
                float2 rr = *(const float2*)&resid[(size_t)mrow * DD + ncol];
                float x0 = accs[mi][n8][half * 2 + 0] + bb.x;
                float x1 = accs[mi][n8][half * 2 + 1] + bb.y;
                float v0 = 0.5f * x0 * (1.0f + erff(x0 * 0.70710678118654752f)) + rr.x;
                float v1 = 0.5f * x1 * (1.0f + erff(x1 * 0.70710678118654752f)) + rr.y;
                *(float2*)&C[(size_t)mrow * DD + ncol] = make_float2(v0, v1);
            }
        }
    }
}

// ---------------------------------------------------------------------------
// HMMA attention, 512 threads (16 warps) — exact R13 version.
// ---------------------------------------------------------------------------
#define ASM_Q_HI 0
#define ASM_Q_LO 32768
#define ASM_K_HI 65536
#define ASM_K_LO 98304
#define ASM_V_HI 131072
#define ASM_V_LO 163840
#define ASM_STAT 196608
#define ASM_SPART 197632
#define ASM_P_HI 0
#define ASM_P_LO 8192
#define ATTN_SMEM (197632 + 64 * 68 * 4)   // 215040

__global__ void __launch_bounds__(512, 1) attn_hmma(
    const __nv_bfloat16* __restrict__ Qhi, const __nv_bfloat16* __restrict__ Qlo,
    const __nv_bfloat16* __restrict__ Khi, const __nv_bfloat16* __restrict__ Klo,
    const __nv_bfloat16* __restrict__ Vhi, const __nv_bfloat16* __restrict__ Vlo,
    __nv_bfloat16* __restrict__ Ohi, __nv_bfloat16* __restrict__ Olo)
{
    extern __shared__ char smem[];
    const uint32_t sbase = smem_to_u32(smem);
    const int t = threadIdx.x;
    const int wid = t >> 5, lane = t & 31;
    const int wk = wid >> 3;
    const int wid7 = wid & 7;
    const int wm = wid7 >> 1, wn = wid7 & 1;
    const int q  = lane >> 3, r8 = lane & 7;
    const size_t base = (size_t)blockIdx.x * SS * DD;

    {
        const __nv_bfloat16* srcs[6] = { Qhi + base, Qlo + base, Khi + base,
                                         Klo + base, Vhi + base, Vlo + base };
        const int dsts[6] = { ASM_Q_HI, ASM_Q_LO, ASM_K_HI, ASM_K_LO, ASM_V_HI, ASM_V_LO };
#pragma unroll
        for (int a = 0; a < 6; a++) {
            const uint32_t dbase = sbase + dsts[a];
            const __nv_bfloat16* src = srcs[a];
#pragma unroll
            for (int g = 0; g < 4; g++) {
                int idx = g * 512 + t;
                int row = idx >> 5;
                int u = idx & 31;
                uint32_t d = row * 512 + ((u ^ (row & 7)) << 4);
                CP_ASYNC16(dbase + d, (const void*)(src + row * DD + u * 8));
            }
        }
    }
    CP_COMMIT();
    CP_WAIT0();
    __syncthreads();

    // ---- S-phase: each group covers k16 wk*8 .. wk*8+7 ----
    const int arow = wm * 16 + r8 + (q & 1) * 8;
    const int a_ku = q >> 1;
    int brow[2];
#pragma unroll
    for (int ni = 0; ni < 2; ni++) brow[ni] = wn * 32 + ni * 16 + r8 + (q >> 1) * 8;
    const int b_ku = q & 1;

    float sacc[4][4];
#pragma unroll
    for (int i = 0; i < 4; i++)
#pragma unroll
        for (int c = 0; c < 4; c++) sacc[i][c] = 0.0f;

    const uint32_t qhb = sbase + ASM_Q_HI, qlb = sbase + ASM_Q_LO;
    const uint32_t khb = sbase + ASM_K_HI, klb = sbase + ASM_K_LO;
#pragma unroll
    for (int kq16 = 0; kq16 < 8; kq16++) {
        const int ku = (wk * 8 + kq16) * 2;
        uint32_t afh[4], afl[4], bfh[2][4], bfl[2][4];
        uint32_t aoff = arow * 512 + (((ku + a_ku) ^ (arow & 7)) << 4);
        ldsm4(afh, qhb + aoff);
        ldsm4(afl, qlb + aoff);
#pragma unroll
        for (int ni = 0; ni < 2; ni++) {
            uint32_t boff = brow[ni] * 512 + (((ku + b_ku) ^ (brow[ni] & 7)) << 4);
            ldsm4(bfh[ni], khb + boff);
            ldsm4(bfl[ni], klb + boff);
        }
        mma16816(sacc[0], afh, &bfh[0][0]);
        mma16816(sacc[1], afh, &bfh[0][2]);
        mma16816(sacc[2], afh, &bfh[1][0]);
        mma16816(sacc[3], afh, &bfh[1][2]);
        mma16816(sacc[0], afh, &bfl[0][0]);
        mma16816(sacc[1], afh, &bfl[0][2]);
        mma16816(sacc[2], afh, &bfl[1][0]);
        mma16816(sacc[3], afh, &bfl[1][2]);
        mma16816(sacc[0], afl, &bfh[0][0]);
        mma16816(sacc[1], afl, &bfh[0][2]);
        mma16816(sacc[2], afl, &bfh[1][0]);
        mma16816(sacc[3], afl, &bfh[1][2]);
    }

    const int fr = lane >> 2;
    const int fc = (lane & 3) * 2;
    const int row0 = wm * 16 + fr;
    const int row1 = row0 + 8;

    float* Sp = (float*)(smem + ASM_SPART);   // [64][68]
    if (wk == 1) {
#pragma unroll
        for (int n8 = 0; n8 < 4; n8++) {
            const int col = wn * 32 + n8 * 8 + fc;
            Sp[row0 * 68 + col]     = sacc[n8][0];
            Sp[row0 * 68 + col + 1] = sacc[n8][1];
            Sp[row1 * 68 + col]     = sacc[n8][2];
            Sp[row1 * 68 + col + 1] = sacc[n8][3];
        }
    }
    __syncthreads();
    if (wk == 0) {
#pragma unroll
        for (int n8 = 0; n8 < 4; n8++) {
            const int col = wn * 32 + n8 * 8 + fc;
            sacc[n8][0] += Sp[row0 * 68 + col];
            sacc[n8][1] += Sp[row0 * 68 + col + 1];
            sacc[n8][2] += Sp[row1 * 68 + col];
            sacc[n8][3] += Sp[row1 * 68 + col + 1];
        }
    }

    float* stat = (float*)(smem + ASM_STAT);

#pragma unroll
    for (int n8 = 0; n8 < 4; n8++)
#pragma unroll
        for (int c = 0; c < 4; c++) sacc[n8][c] *= 0.0625f;

    float m0 = -1e30f, m1 = -1e30f;
#pragma unroll
    for (int n8 = 0; n8 < 4; n8++) {
        m0 = fmaxf(m0, fmaxf(sacc[n8][0], sacc[n8][1]));
        m1 = fmaxf(m1, fmaxf(sacc[n8][2], sacc[n8][3]));
    }
    m0 = fmaxf(m0, __shfl_xor_sync(0xffffffffu, m0, 1));
    m0 = fmaxf(m0, __shfl_xor_sync(0xffffffffu, m0, 2));
    m1 = fmaxf(m1, __shfl_xor_sync(0xffffffffu, m1, 1));
    m1 = fmaxf(m1, __shfl_xor_sync(0xffffffffu, m1, 2));
    if (wk == 0 && (lane & 3) == 0) {
        stat[row0 * 2 + wn] = m0;
        stat[row1 * 2 + wn] = m1;
    }
    __syncthreads();
    m0 = fmaxf(stat[row0 * 2], stat[row0 * 2 + 1]);
    m1 = fmaxf(stat[row1 * 2], stat[row1 * 2 + 1]);

    float s0 = 0.0f, s1 = 0.0f;
#pragma unroll
    for (int n8 = 0; n8 < 4; n8++) {
        float p0 = expf(sacc[n8][0] - m0); sacc[n8][0] = p0;
        float p1 = expf(sacc[n8][1] - m0); sacc[n8][1] = p1;
        float p2 = expf(sacc[n8][2] - m1); sacc[n8][2] = p2;
        float p3 = expf(sacc[n8][3] - m1); sacc[n8][3] = p3;
        s0 += p0 + p1; s1 += p2 + p3;
    }
    s0 += __shfl_xor_sync(0xffffffffu, s0, 1);
    s0 += __shfl_xor_sync(0xffffffffu, s0, 2);
    s1 += __shfl_xor_sync(0xffffffffu, s1, 1);
    s1 += __shfl_xor_sync(0xffffffffu, s1, 2);
    if (wk == 0 && (lane & 3) == 0) {
        stat[128 + row0 * 2 + wn] = s0;
        stat[128 + row1 * 2 + wn] = s1;
    }
    __syncthreads();
    const float inv0 = 1.0f / (stat[128 + row0 * 2] + stat[128 + row0 * 2 + 1]);
    const float inv1 = 1.0f / (stat[128 + row1 * 2] + stat[128 + row1 * 2 + 1]);

    if (wk == 0) {
        char* phi = smem + ASM_P_HI;
        char* plo = smem + ASM_P_LO;
#pragma unroll
        for (int n8 = 0; n8 < 4; n8++) {
            const int j = wn * 32 + n8 * 8 + fc;
            const int u = j >> 3, b = (j & 7) * 2;
            float p0 = sacc[n8][0] * inv0, p1 = sacc[n8][1] * inv0;
            uint32_t hw, lw;
            split2(p0, p1, hw, lw);
            int off0 = row0 * 128 + ((u ^ (row0 & 7)) << 4) + b;
            *(uint32_t*)(phi + off0) = hw;
            *(uint32_t*)(plo + off0) = lw;
            float p2 = sacc[n8][2] * inv1, p3 = sacc[n8][3] * inv1;
            split2(p2, p3, hw, lw);
            int off1 = row1 * 128 + ((u ^ (row1 & 7)) << 4) + b;
            *(uint32_t*)(phi + off1) = hw;
            *(uint32_t*)(plo + off1) = lw;
        }
    }
    __syncthreads();

    const int wm2 = wid >> 2;
    const int wd  = wid & 3;
    float oacc[8][4];
#pragma unroll
    for (int i = 0; i < 8; i++)
#pragma unroll
        for (int c = 0; c < 4; c++) oacc[i][c] = 0.0f;

    const uint32_t phb = sbase + ASM_P_HI;
    const uint32_t plb = sbase + ASM_P_LO;
    const uint32_t vhb = sbase + ASM_V_HI;
    const uint32_t vlb = sbase + ASM_V_LO;
    const int arow2 = wm2 * 16 + r8 + (q & 1) * 8;

#pragma unroll
    for (int k16 = 0; k16 < 4; k16++) {
        uint32_t ph[4], pl[4];
        uint32_t aoff = arow2 * 128 + (((k16 * 2 + a_ku) ^ (arow2 & 7)) << 4);
        ldsm4(ph, phb + aoff);
        ldsm4(pl, plb + aoff);
        const int jrow = k16 * 16 + (q & 1) * 8 + r8;
#pragma unroll
        for (int dp = 0; dp < 2; dp++) {
            uint32_t vh0[4], vl0[4], vh1[4], vl1[4];
            const int u0 = wd * 8 + (dp * 2) * 2 + (q >> 1);
            const int u1 = wd * 8 + (dp * 2 + 1) * 2 + (q >> 1);
            uint32_t voff0 = jrow * 512 + ((u0 ^ (jrow & 7)) << 4);
            uint32_t voff1 = jrow * 512 + ((u1 ^ (jrow & 7)) << 4);
            ldsm4t(vh0, vhb + voff0);
            ldsm4t(vl0, vlb + voff0);
            ldsm4t(vh1, vhb + voff1);
            ldsm4t(vl1, vlb + voff1);
            float* o0 = oacc[dp * 4 + 0];
            float* o1 = oacc[dp * 4 + 1];
            float* o2 = oacc[dp * 4 + 2];
            float* o3 = oacc[dp * 4 + 3];
            mma16816(o0, ph, &vh0[0]);  mma16816(o1, ph, &vh0[2]);
            mma16816(o2, ph, &vh1[0]);  mma16816(o3, ph, &vh1[2]);
            mma16816(o0, ph, &vl0[0]);  mma16816(o1, ph, &vl0[2]);
            mma16816(o2, ph, &vl1[0]);  mma16816(o3, ph, &vl1[2]);
            mma16816(o0, pl, &vh0[0]);  mma16816(o1, pl, &vh0[2]);
            mma16816(o2, pl, &vh1[0]);  mma16816(o3, pl, &vh1[2]);
        }
    }

    const int prow0 = wm2 * 16 + fr;
    const int prow1 = prow0 + 8;
#pragma unroll
    for (int n8 = 0; n8 < 8; n8++) {
        const int d = wd * 64 + n8 * 8 + fc;
        uint32_t hw, lw;
        split2(oacc[n8][0], oacc[n8][1], hw, lw);
        *(uint32_t*)&Ohi[base + (size_t)prow0 * DD + d] = hw;
        *(uint32_t*)&Olo[base + (size_t)prow0 * DD + d] = lw;
        split2(oacc[n8][2], oacc[n8][3], hw, lw);
        *(uint32_t*)&Ohi[base + (size_t)prow1 * DD + d] = hw;
        *(uint32_t*)&Olo[base + (size_t)prow1 * DD + d] = lw;
    }
}

// ---------------------------------------------------------------------------
extern "C" void kernel_launch(void* const* d_in, const int* in_sizes, int n_in,
                              void* d_out, int out_size) {
    (void)in_sizes; (void)n_in; (void)out_size;
    const float* q  = (const float*)d_in[0];
    const float* k  = (const float*)d_in[1];
    const float* v  = (const float*)d_in[2];
    const float* Wq = (const float*)d_in[3];
    const float* Wk = (const float*)d_in[4];
    const float* Wv = (const float*)d_in[5];
    const float* Wo = (const float*)d_in[6];
    const float* bo = (const float*)d_in[7];
    float* out = (float*)d_out;

    __nv_bfloat16 *qhi, *qlo, *khi, *klo, *vhi, *vlo, *aohi, *aolo, *whi, *wlo;
    cudaGetSymbolAddress((void**)&qhi, g_qhi);
    cudaGetSymbolAddress((void**)&qlo, g_qlo);
    cudaGetSymbolAddress((void**)&khi, g_khi);
    cudaGetSymbolAddress((void**)&klo, g_klo);
    cudaGetSymbolAddress((void**)&vhi, g_vhi);
    cudaGetSymbolAddress((void**)&vlo, g_vlo);
    cudaGetSymbolAddress((void**)&aohi, g_aohi);
    cudaGetSymbolAddress((void**)&aolo, g_aolo);
    cudaGetSymbolAddress((void**)&whi, g_w_hi);
    cudaGetSymbolAddress((void**)&wlo, g_w_lo);

    prep_kernel<<<64 + 1024, 256>>>(Wq, Wk, Wv, Wo, whi, wlo);

    cudaFuncSetAttribute(gemm_qkv, cudaFuncAttributeMaxDynamicSharedMemorySize, GSMEM_TOTAL);
    cudaFuncSetAttribute(gemm_out, cudaFuncAttributeMaxDynamicSharedMemorySize, GSMEM_TOTAL);
    cudaFuncSetAttribute(attn_hmma, cudaFuncAttributeMaxDynamicSharedMemorySize, ATTN_SMEM);

    dim3 gg(M_TOTAL / 128, 2, 3);
    gemm_qkv<<<gg, 256, GSMEM_TOTAL>>>(q, k, v, whi, wlo,
                                       qhi, qlo, khi, klo, vhi, vlo);

    attn_hmma<<<VIEWS, 512, ATTN_SMEM>>>(qhi, qlo, khi, klo, vhi, vlo, aohi, aolo);

    dim3 go(M_TOTAL / 128, 2);
    gemm_out<<<go, 256, GSMEM_TOTAL>>>(aohi, aolo, whi + 3 * DD * DD, wlo + 3 * DD * DD,
                                       out, bo, q);
}

// round 16
// speedup vs baseline: 1.0377x; 1.0329x over previous
#include <cuda_runtime.h>
#include <cuda_bf16.h>
#include <math.h>
#include <stdint.h>
#include <string.h>

#define VIEWS 1024
#define SS 64
#define DD 256
#define M_TOTAL (VIEWS * SS)   // 65536

// ---------------------------------------------------------------------------
// Scratch (allocation-free rule: __device__ globals). Activations as bf16 hi/lo.
// ---------------------------------------------------------------------------
__device__ __align__(256) __nv_bfloat16 g_qhi[(size_t)M_TOTAL * DD];
__device__ __align__(256) __nv_bfloat16 g_qlo[(size_t)M_TOTAL * DD];
__device__ __align__(256) __nv_bfloat16 g_khi[(size_t)M_TOTAL * DD];
__device__ __align__(256) __nv_bfloat16 g_klo[(size_t)M_TOTAL * DD];
__device__ __align__(256) __nv_bfloat16 g_vhi[(size_t)M_TOTAL * DD];
__device__ __align__(256) __nv_bfloat16 g_vlo[(size_t)M_TOTAL * DD];
__device__ __align__(256) __nv_bfloat16 g_aohi[(size_t)M_TOTAL * DD];
__device__ __align__(256) __nv_bfloat16 g_aolo[(size_t)M_TOTAL * DD];
__device__ float g_pe[SS * DD];
__device__ __align__(256) __nv_bfloat16 g_w_hi[4][DD * DD];
__device__ __align__(256) __nv_bfloat16 g_w_lo[4][DD * DD];

// ---------------------------------------------------------------------------
// PTX helpers
// ---------------------------------------------------------------------------
__device__ __forceinline__ uint32_t smem_to_u32(const void* p) {
    uint32_t a;
    asm("{ .reg .u64 t; cvta.to.shared.u64 t, %1; cvt.u32.u64 %0, t; }"
        : "=r"(a) : "l"(p));
    return a;
}
#define CP_ASYNC16(dst_u32, src_ptr) \
    asm volatile("cp.async.cg.shared.global [%0], [%1], 16;" \
        :: "r"(dst_u32), "l"(src_ptr))
#define CP_COMMIT() asm volatile("cp.async.commit_group;" ::: "memory")
#define CP_WAIT0()  asm volatile("cp.async.wait_group 0;" ::: "memory")
#define CP_WAIT1()  asm volatile("cp.async.wait_group 1;" ::: "memory")

__device__ __forceinline__ void ldsm4(uint32_t* r, uint32_t addr) {
    asm volatile("ldmatrix.sync.aligned.m8n8.x4.shared.b16 {%0,%1,%2,%3}, [%4];"
        : "=r"(r[0]), "=r"(r[1]), "=r"(r[2]), "=r"(r[3]) : "r"(addr));
}
__device__ __forceinline__ void ldsm4t(uint32_t* r, uint32_t addr) {
    asm volatile("ldmatrix.sync.aligned.m8n8.x4.trans.shared.b16 {%0,%1,%2,%3}, [%4];"
        : "=r"(r[0]), "=r"(r[1]), "=r"(r[2]), "=r"(r[3]) : "r"(addr));
}
__device__ __forceinline__ void mma16816(float* c, const uint32_t* a, const uint32_t* b) {
    asm volatile(
        "mma.sync.aligned.m16n8k16.row.col.f32.bf16.bf16.f32 "
        "{%0,%1,%2,%3}, {%4,%5,%6,%7}, {%8,%9}, {%0,%1,%2,%3};"
        : "+f"(c[0]), "+f"(c[1]), "+f"(c[2]), "+f"(c[3])
        : "r"(a[0]), "r"(a[1]), "r"(a[2]), "r"(a[3]), "r"(b[0]), "r"(b[1]));
}

__device__ __forceinline__ uint32_t pack2bf(float a, float b) {
    __nv_bfloat162 h = __floats2bfloat162_rn(a, b);
    uint32_t u; memcpy(&u, &h, 4); return u;
}
__device__ __forceinline__ void split2(float a, float b, uint32_t& hw, uint32_t& lw) {
    __nv_bfloat16 ha = __float2bfloat16_rn(a);
    __nv_bfloat16 hb = __float2bfloat16_rn(b);
    uint16_t ua, ub; memcpy(&ua, &ha, 2); memcpy(&ub, &hb, 2);
    hw = (uint32_t)ua | ((uint32_t)ub << 16);
    lw = pack2bf(a - __bfloat162float(ha), b - __bfloat162float(hb));
}

// ---------------------------------------------------------------------------
// Prep: posenc + all 4 weight splits in ONE launch
// ---------------------------------------------------------------------------
__global__ void prep_kernel(const float* __restrict__ Wq, const float* __restrict__ Wk,
                            const float* __restrict__ Wv, const float* __restrict__ Wo,
                            __nv_bfloat16* __restrict__ whi, __nv_bfloat16* __restrict__ wlo) {
    int b = blockIdx.x;
    int t = threadIdx.x;
    if (b < 64) {
        int idx = b * 256 + t;
        int s = idx / DD;
        int d = idx % DD;
        double angle = (double)s / pow(10000.0, (2.0 * (double)(d / 2)) / (double)DD);
        g_pe[idx] = (d & 1) ? (float)cos(angle) : (float)sin(angle);
    } else {
        int idx = (b - 64) * 256 + t;
        int w = idx >> 16;
        int i = idx & 65535;
        const float* W = (w == 0) ? Wq : (w == 1) ? Wk : (w == 2) ? Wv : Wo;
        float x = W[i];
        __nv_bfloat16 h = __float2bfloat16_rn(x);
        whi[(size_t)w * 65536 + i] = h;
        wlo[(size_t)w * 65536 + i] = __float2bfloat16_rn(x - __bfloat162float(h));
    }
}

// ---------------------------------------------------------------------------
// GEMM geometry (R13-validated): CTA tile 128x128, 256 thr, 8 warps (4m x 2n),
// warp tile 32x64. K = 8 chunks of 32, 2 stages of 32 KB.
// Inner: frag reuse + TERM-MAJOR MMA ordering (acc reuse distance 8).
// ---------------------------------------------------------------------------
#define GSTAGE 32768
#define GSMEM_TOTAL (2 * GSTAGE)
#define SWZ(r) (((r) >> 1) & 3)

#define TERM8(ACC, AF, BF, NH) \
    mma16816(ACC[0][(NH)*4 + 0], AF[0], &BF[0][0]); \
    mma16816(ACC[0][(NH)*4 + 1], AF[0], &BF[0][2]); \
    mma16816(ACC[0][(NH)*4 + 2], AF[0], &BF[1][0]); \
    mma16816(ACC[0][(NH)*4 + 3], AF[0], &BF[1][2]); \
    mma16816(ACC[1][(NH)*4 + 0], AF[1], &BF[0][0]); \
    mma16816(ACC[1][(NH)*4 + 1], AF[1], &BF[0][2]); \
    mma16816(ACC[1][(NH)*4 + 2], AF[1], &BF[1][0]); \
    mma16816(ACC[1][(NH)*4 + 3], AF[1], &BF[1][2]);

// ---- gemm_qkv FUSED over z=0,1,2 (q,k,v). Pointer select is uniform. ----
__global__ void __launch_bounds__(256, 2) gemm_qkv(
    const float* __restrict__ A0, const float* __restrict__ A1,
    const float* __restrict__ A2,
    const __nv_bfloat16* __restrict__ WhiB,
    const __nv_bfloat16* __restrict__ WloB,
    __nv_bfloat16* __restrict__ C0h, __nv_bfloat16* __restrict__ C0l,
    __nv_bfloat16* __restrict__ C1h, __nv_bfloat16* __restrict__ C1l,
    __nv_bfloat16* __restrict__ C2h, __nv_bfloat16* __restrict__ C2l)
{
    extern __shared__ char smem[];
    const uint32_t sbase = smem_to_u32(smem);
    const int t = threadIdx.x;
    const int wid = t >> 5, lane = t & 31;
    const int wm = wid >> 1, wn = wid & 1;
    const int m0 = blockIdx.x << 7;
    const int N0 = blockIdx.y << 7;
    const int z  = blockIdx.z;

    const float* A = (z == 0) ? A0 : (z == 1) ? A1 : A2;
    const __nv_bfloat16* Whi = WhiB + (size_t)z * 65536;
    const __nv_bfloat16* Wlo = WloB + (size_t)z * 65536;
    __nv_bfloat16* Chi = (z == 0) ? C0h : (z == 1) ? C1h : C2h;
    __nv_bfloat16* Clo = (z == 0) ? C0l : (z == 1) ? C1l : C2l;

    float accs[2][8][4];
    float* acc[2][8];
#pragma unroll
    for (int i = 0; i < 2; i++)
#pragma unroll
        for (int j = 0; j < 8; j++) {
            acc[i][j] = accs[i][j];
#pragma unroll
            for (int c = 0; c < 4; c++) accs[i][j][c] = 0.0f;
        }

    auto load_B = [&](int kc, int s) {
        const uint32_t bhi = sbase + s * GSTAGE + 16384;
        const uint32_t blo = bhi + 8192;
#pragma unroll
        for (int g = 0; g < 2; g++) {
            int idx = g * 256 + t;
            int nrow = idx >> 2;
            int u = idx & 3;
            size_t goff = (size_t)(N0 + nrow) * DD + kc * 32 + u * 8;
            uint32_t d = (uint32_t)(nrow * 64 + ((u ^ SWZ(nrow)) << 4));
            CP_ASYNC16(bhi + d, (const void*)(Whi + goff));
            CP_ASYNC16(blo + d, (const void*)(Wlo + goff));
        }
    };

    float4 areg[4];
    auto load_A = [&](int kc) {
#pragma unroll
        for (int g = 0; g < 4; g++) {
            int idx = g * 256 + t;
            int row = idx >> 3;
            int f4c = idx & 7;
            areg[g] = *(const float4*)(A + (size_t)(m0 + row) * DD + kc * 32 + f4c * 4);
        }
    };
    auto store_A = [&](int s) {
        char* ahi = smem + s * GSTAGE;
        char* alo = ahi + 8192;
#pragma unroll
        for (int g = 0; g < 4; g++) {
            int idx = g * 256 + t;
            int row = idx >> 3;
            int f4c = idx & 7;
            float4 v = areg[g];
            uint32_t h01, l01, h23, l23;
            split2(v.x, v.y, h01, l01);
            split2(v.z, v.w, h23, l23);
            uint64_t hi64 = (uint64_t)h01 | ((uint64_t)h23 << 32);
            uint64_t lo64 = (uint64_t)l01 | ((uint64_t)l23 << 32);
            int u = f4c >> 1, half = f4c & 1;
            int d = row * 64 + ((u ^ SWZ(row)) << 4) + half * 8;
            *(uint64_t*)(ahi + d) = hi64;
            *(uint64_t*)(alo + d) = lo64;
        }
    };

    load_B(0, 0);
    CP_COMMIT();
    load_A(0);
    store_A(0);

    const int q  = lane >> 3;
    const int r8 = lane & 7;
    int arow[2], brow[4];
#pragma unroll
    for (int mi = 0; mi < 2; mi++) arow[mi] = wm * 32 + mi * 16 + r8 + (q & 1) * 8;
#pragma unroll
    for (int ni = 0; ni < 4; ni++) brow[ni] = wn * 64 + ni * 16 + r8 + (q >> 1) * 8;
    const int a_kq = q >> 1;
    const int b_kq = q & 1;

    for (int kc = 0; kc < 8; kc++) {
        const int s = kc & 1;
        CP_WAIT0();
        __syncthreads();
        if (kc < 7) {
            load_B(kc + 1, s ^ 1);
            CP_COMMIT();
            load_A(kc + 1);
        }
        const uint32_t ah = sbase + s * GSTAGE;
        const uint32_t al = ah + 8192;
        const uint32_t bh = ah + 16384;
        const uint32_t bl = ah + 24576;
#pragma unroll
        for (int k16 = 0; k16 < 2; k16++) {
            uint32_t afh[2][4], afl[2][4];
#pragma unroll
            for (int mi = 0; mi < 2; mi++) {
                int ku = k16 * 2 + a_kq;
                uint32_t off = arow[mi] * 64 + ((ku ^ SWZ(arow[mi])) << 4);
                ldsm4(afh[mi], ah + off);
                ldsm4(afl[mi], al + off);
            }
#pragma unroll
            for (int nh = 0; nh < 2; nh++) {
                uint32_t bfh[2][4], bfl[2][4];
#pragma unroll
                for (int nj = 0; nj < 2; nj++) {
                    int ni = nh * 2 + nj;
                    int ku = k16 * 2 + b_kq;
                    uint32_t off = brow[ni] * 64 + ((ku ^ SWZ(brow[ni])) << 4);
                    ldsm4(bfh[nj], bh + off);
                    ldsm4(bfl[nj], bl + off);
                }
                TERM8(acc, afh, bfh, nh)
                TERM8(acc, afh, bfl, nh)
                TERM8(acc, afl, bfh, nh)
            }
        }
        if (kc < 7) store_A(s ^ 1);
    }

    const int fr = lane >> 2;
    const int fc = (lane & 3) * 2;
#pragma unroll
    for (int mi = 0; mi < 2; mi++) {
#pragma unroll
        for (int half = 0; half < 2; half++) {
            const int mrow = m0 + wm * 32 + mi * 16 + fr + half * 8;
            const int sr = mrow & (SS - 1);
#pragma unroll
            for (int n8 = 0; n8 < 8; n8++) {
                const int ncol = N0 + wn * 64 + n8 * 8 + fc;
                float2 pe = *(const float2*)&g_pe[sr * DD + ncol];
                float v0 = accs[mi][n8][half * 2 + 0] + pe.x;
                float v1 = accs[mi][n8][half * 2 + 1] + pe.y;
                uint32_t hw, lw;
                split2(v0, v1, hw, lw);
                *(uint32_t*)&Chi[(size_t)mrow * DD + ncol] = hw;
                *(uint32_t*)&Clo[(size_t)mrow * DD + ncol] = lw;
            }
        }
    }
}

// ---- gemm_out: A pre-split bf16 via cp.async; fp32 out with gelu+resid ----
__global__ void __launch_bounds__(256, 2) gemm_out(
    const __nv_bfloat16* __restrict__ Ahi,
    const __nv_bfloat16* __restrict__ Alo,
    const __nv_bfloat16* __restrict__ Whi,
    const __nv_bfloat16* __restrict__ Wlo,
    float* __restrict__ C,
    const float* __restrict__ bias,
    const float* __restrict__ resid)
{
    extern __shared__ char smem[];
    const uint32_t sbase = smem_to_u32(smem);
    const int t = threadIdx.x;
    const int wid = t >> 5, lane = t & 31;
    const int wm = wid >> 1, wn = wid & 1;
    const int m0 = blockIdx.x << 7;
    const int N0 = blockIdx.y << 7;

    float accs[2][8][4];
    float* acc[2][8];
#pragma unroll
    for (int i = 0; i < 2; i++)
#pragma unroll
        for (int j = 0; j < 8; j++) {
            acc[i][j] = accs[i][j];
#pragma unroll
            for (int c = 0; c < 4; c++) accs[i][j][c] = 0.0f;
        }

    auto load_AB = [&](int kc, int s) {
        const uint32_t ahi = sbase + s * GSTAGE;
        const uint32_t alo = ahi + 8192;
        const uint32_t bhi = ahi + 16384;
        const uint32_t blo = ahi + 24576;
#pragma unroll
        for (int g = 0; g < 2; g++) {
            int idx = g * 256 + t;
            int row = idx >> 2;
            int u = idx & 3;
            uint32_t d = (uint32_t)(row * 64 + ((u ^ SWZ(row)) << 4));
            size_t goffa = (size_t)(m0 + row) * DD + kc * 32 + u * 8;
            CP_ASYNC16(ahi + d, (const void*)(Ahi + goffa));
            CP_ASYNC16(alo + d, (const void*)(Alo + goffa));
            size_t goffb = (size_t)(N0 + row) * DD + kc * 32 + u * 8;
            CP_ASYNC16(bhi + d, (const void*)(Whi + goffb));
            CP_ASYNC16(blo + d, (const void*)(Wlo + goffb));
        }
    };

    load_AB(0, 0);
    CP_COMMIT();

    const int q  = lane >> 3;
    const int r8 = lane & 7;
    int arow[2], brow[4];
#pragma unroll
    for (int mi = 0; mi < 2; mi++) arow[mi] = wm * 32 + mi * 16 + r8 + (q & 1) * 8;
#pragma unroll
    for (int ni = 0; ni < 4; ni++) brow[ni] = wn * 64 + ni * 16 + r8 + (q >> 1) * 8;
    const int a_kq = q >> 1;
    const int b_kq = q & 1;

    for (int kc = 0; kc < 8; kc++) {
        const int s = kc & 1;
        CP_WAIT0();
        __syncthreads();
        if (kc < 7) {
            load_AB(kc + 1, s ^ 1);
            CP_COMMIT();
        }
        const uint32_t ah = sbase + s * GSTAGE;
        const uint32_t al = ah + 8192;
        const uint32_t bh = ah + 16384;
        const uint32_t bl = ah + 24576;
#pragma unroll
        for (int k16 = 0; k16 < 2; k16++) {
            uint32_t afh[2][4], afl[2][4];
#pragma unroll
            for (int mi = 0; mi < 2; mi++) {
                int ku = k16 * 2 + a_kq;
                uint32_t off = arow[mi] * 64 + ((ku ^ SWZ(arow[mi])) << 4);
                ldsm4(afh[mi], ah + off);
                ldsm4(afl[mi], al + off);
            }
#pragma unroll
            for (int nh = 0; nh < 2; nh++) {
                uint32_t bfh[2][4], bfl[2][4];
#pragma unroll
                for (int nj = 0; nj < 2; nj++) {
                    int ni = nh * 2 + nj;
                    int ku = k16 * 2 + b_kq;
                    uint32_t off = brow[ni] * 64 + ((ku ^ SWZ(brow[ni])) << 4);
                    ldsm4(bfh[nj], bh + off);
                    ldsm4(bfl[nj], bl + off);
                }
                TERM8(acc, afh, bfh, nh)
                TERM8(acc, afh, bfl, nh)
                TERM8(acc, afl, bfh, nh)
            }
        }
    }

    const int fr = lane >> 2;
    const int fc = (lane & 3) * 2;
#pragma unroll
    for (int mi = 0; mi < 2; mi++) {
#pragma unroll
        for (int half = 0; half < 2; half++) {
            const int mrow = m0 + wm * 32 + mi * 16 + fr + half * 8;
#pragma unroll
            for (int n8 = 0; n8 < 8; n8++) {
                const int ncol = N0 + wn * 64 + n8 * 8 + fc;
                float2 bb = *(const float2*)&bias[ncol];
                float2 rr = *(const float2*)&resid[(size_t)mrow * DD + ncol];
                float x0 = accs[mi][n8][half * 2 + 0] + bb.x;
                float x1 = accs[mi][n8][half * 2 + 1] + bb.y;
                float v0 = 0.5f * x0 * (1.0f + erff(x0 * 0.70710678118654752f)) + rr.x;
                float v1 = 0.5f * x1 * (1.0f + erff(x1 * 0.70710678118654752f)) + rr.y;
                *(float2*)&C[(size_t)mrow * DD + ncol] = make_float2(v0, v1);
            }
        }
    }
}

// ---------------------------------------------------------------------------
// HMMA attention, 512 threads (16 warps):
//   NEW: group-private chunked loads. Warp-group wk loads ONLY its Q/K d-chunk
//   (cols wk*128..wk*128+127), then waits on its own commit + named barrier
//   and starts S-phase immediately. V is a second per-thread commit, drained
//   (wait_group 0 + __syncthreads) just before P@V.
// ---------------------------------------------------------------------------
#define ASM_Q_HI 0
#define ASM_Q_LO 32768
#define ASM_K_HI 65536
#define ASM_K_LO 98304
#define ASM_V_HI 131072
#define ASM_V_LO 163840
#define ASM_STAT 196608
#define ASM_SPART 197632
#define ASM_P_HI 0
#define ASM_P_LO 8192
#define ATTN_SMEM (197632 + 64 * 68 * 4)   // 215040

__global__ void __launch_bounds__(512, 1) attn_hmma(
    const __nv_bfloat16* __restrict__ Qhi, const __nv_bfloat16* __restrict__ Qlo,
    const __nv_bfloat16* __restrict__ Khi, const __nv_bfloat16* __restrict__ Klo,
    const __nv_bfloat16* __restrict__ Vhi, const __nv_bfloat16* __restrict__ Vlo,
    __nv_bfloat16* __restrict__ Ohi, __nv_bfloat16* __restrict__ Olo)
{
    extern __shared__ char smem[];
    const uint32_t sbase = smem_to_u32(smem);
    const int t = threadIdx.x;
    const int wid = t >> 5, lane = t & 31;
    const int wk = wid >> 3;
    const int wid7 = wid & 7;
    const int wm = wid7 >> 1, wn = wid7 & 1;
    const int q  = lane >> 3, r8 = lane & 7;
    const size_t base = (size_t)blockIdx.x * SS * DD;

    // ---- Group-private Q/K chunk load: group wk loads u in [wk*16, wk*16+16) ----
    {
        const int gt = t & 255;            // tid within group
        const __nv_bfloat16* srcs[4] = { Qhi + base, Qlo + base, Khi + base, Klo + base };
        const int dsts[4] = { ASM_Q_HI, ASM_Q_LO, ASM_K_HI, ASM_K_LO };
#pragma unroll
        for (int a = 0; a < 4; a++) {
            const uint32_t dbase = sbase + dsts[a];
            const __nv_bfloat16* src = srcs[a];
#pragma unroll
            for (int g = 0; g < 4; g++) {
                int idx = g * 256 + gt;     // 0..1023 = 64 rows x 16 granules
                int row = idx >> 4;
                int u = (idx & 15) + wk * 16;
                uint32_t d = row * 512 + ((u ^ (row & 7)) << 4);
                CP_ASYNC16(dbase + d, (const void*)(src + row * DD + u * 8));
            }
        }
    }
    CP_COMMIT();
    // ---- V load: all 512 threads, second per-thread commit group ----
    {
        const __nv_bfloat16* srcs2[2] = { Vhi + base, Vlo + base };
        const int dsts2[2] = { ASM_V_HI, ASM_V_LO };
#pragma unroll
        for (int a = 0; a < 2; a++) {
            const uint32_t dbase = sbase + dsts2[a];
            const __nv_bfloat16* src = srcs2[a];
#pragma unroll
            for (int g = 0; g < 4; g++) {
                int idx = g * 512 + t;      // 0..2047 = 64 rows x 32 granules
                int row = idx >> 5;
                int u = idx & 31;
                uint32_t d = row * 512 + ((u ^ (row & 7)) << 4);
                CP_ASYNC16(dbase + d, (const void*)(src + row * DD + u * 8));
            }
        }
    }
    CP_COMMIT();
    CP_WAIT1();                                  // own Q/K chunk done (V pending)
    asm volatile("bar.sync %0, 256;" :: "r"(1 + wk) : "memory");   // group barrier

    // ---- S-phase: each group covers k16 wk*8 .. wk*8+7 (its own chunk) ----
    const int arow = wm * 16 + r8 + (q & 1) * 8;
    const int a_ku = q >> 1;
    int brow[2];
#pragma unroll
    for (int ni = 0; ni < 2; ni++) brow[ni] = wn * 32 + ni * 16 + r8 + (q >> 1) * 8;
    const int b_ku = q & 1;

    float sacc[4][4];
#pragma unroll
    for (int i = 0; i < 4; i++)
#pragma unroll
        for (int c = 0; c < 4; c++) sacc[i][c] = 0.0f;

    const uint32_t qhb = sbase + ASM_Q_HI, qlb = sbase + ASM_Q_LO;
    const uint32_t khb = sbase + ASM_K_HI, klb = sbase + ASM_K_LO;
#pragma unroll
    for (int kq16 = 0; kq16 < 8; kq16++) {
        const int ku = (wk * 8 + kq16) * 2;
        uint32_t afh[4], afl[4], bfh[2][4], bfl[2][4];
        uint32_t aoff = arow * 512 + (((ku + a_ku) ^ (arow & 7)) << 4);
        ldsm4(afh, qhb + aoff);
        ldsm4(afl, qlb + aoff);
#pragma unroll
        for (int ni = 0; ni < 2; ni++) {
            uint32_t boff = brow[ni] * 512 + (((ku + b_ku) ^ (brow[ni] & 7)) << 4);
            ldsm4(bfh[ni], khb + boff);
            ldsm4(bfl[ni], klb + boff);
        }
        mma16816(sacc[0], afh, &bfh[0][0]);
        mma16816(sacc[1], afh, &bfh[0][2]);
        mma16816(sacc[2], afh, &bfh[1][0]);
        mma16816(sacc[3], afh, &bfh[1][2]);
        mma16816(sacc[0], afh, &bfl[0][0]);
        mma16816(sacc[1], afh, &bfl[0][2]);
        mma16816(sacc[2], afh, &bfl[1][0]);
        mma16816(sacc[3], afh, &bfl[1][2]);
        mma16816(sacc[0], afl, &bfh[0][0]);
        mma16816(sacc[1], afl, &bfh[0][2]);
        mma16816(sacc[2], afl, &bfh[1][0]);
        mma16816(sacc[3], afl, &bfh[1][2]);
    }

    const int fr = lane >> 2;
    const int fc = (lane & 3) * 2;
    const int row0 = wm * 16 + fr;
    const int row1 = row0 + 8;

    // ---- reduce group-1 partial into group 0 ----
    float* Sp = (float*)(smem + ASM_SPART);   // [64][68]
    if (wk == 1) {
#pragma unroll
        for (int n8 = 0; n8 < 4; n8++) {
            const int col = wn * 32 + n8 * 8 + fc;
            Sp[row0 * 68 + col]     = sacc[n8][0];
            Sp[row0 * 68 + col + 1] = sacc[n8][1];
            Sp[row1 * 68 + col]     = sacc[n8][2];
            Sp[row1 * 68 + col + 1] = sacc[n8][3];
        }
    }
    __syncthreads();
    if (wk == 0) {
#pragma unroll
        for (int n8 = 0; n8 < 4; n8++) {
            const int col = wn * 32 + n8 * 8 + fc;
            sacc[n8][0] += Sp[row0 * 68 + col];
            sacc[n8][1] += Sp[row0 * 68 + col + 1];
            sacc[n8][2] += Sp[row1 * 68 + col];
            sacc[n8][3] += Sp[row1 * 68 + col + 1];
        }
    }

    // ---- Softmax (group 0 holds full S; all threads run, writes guarded) ----
    float* stat = (float*)(smem + ASM_STAT);

#pragma unroll
    for (int n8 = 0; n8 < 4; n8++)
#pragma unroll
        for (int c = 0; c < 4; c++) sacc[n8][c] *= 0.0625f;

    float m0 = -1e30f, m1 = -1e30f;
#pragma unroll
    for (int n8 = 0; n8 < 4; n8++) {
        m0 = fmaxf(m0, fmaxf(sacc[n8][0], sacc[n8][1]));
        m1 = fmaxf(m1, fmaxf(sacc[n8][2], sacc[n8][3]));
    }
    m0 = fmaxf(m0, __shfl_xor_sync(0xffffffffu, m0, 1));
    m0 = fmaxf(m0, __shfl_xor_sync(0xffffffffu, m0, 2));
    m1 = fmaxf(m1, __shfl_xor_sync(0xffffffffu, m1, 1));
    m1 = fmaxf(m1, __shfl_xor_sync(0xffffffffu, m1, 2));
    if (wk == 0 && (lane & 3) == 0) {
        stat[row0 * 2 + wn] = m0;
        stat[row1 * 2 + wn] = m1;
    }
    __syncthreads();
    m0 = fmaxf(stat[row0 * 2], stat[row0 * 2 + 1]);
    m1 = fmaxf(stat[row1 * 2], stat[row1 * 2 + 1]);

    float s0 = 0.0f, s1 = 0.0f;
#pragma unroll
    for (int n8 = 0; n8 < 4; n8++) {
        float p0 = expf(sacc[n8][0] - m0); sacc[n8][0] = p0;
        float p1 = expf(sacc[n8][1] - m0); sacc[n8][1] = p1;
        float p2 = expf(sacc[n8][2] - m1); sacc[n8][2] = p2;
        float p3 = expf(sacc[n8][3] - m1); sacc[n8][3] = p3;
        s0 += p0 + p1; s1 += p2 + p3;
    }
    s0 += __shfl_xor_sync(0xffffffffu, s0, 1);
    s0 += __shfl_xor_sync(0xffffffffu, s0, 2);
    s1 += __shfl_xor_sync(0xffffffffu, s1, 1);
    s1 += __shfl_xor_sync(0xffffffffu, s1, 2);
    if (wk == 0 && (lane & 3) == 0) {
        stat[128 + row0 * 2 + wn] = s0;
        stat[128 + row1 * 2 + wn] = s1;
    }
    __syncthreads();
    const float inv0 = 1.0f / (stat[128 + row0 * 2] + stat[128 + row0 * 2 + 1]);
    const float inv1 = 1.0f / (stat[128 + row1 * 2] + stat[128 + row1 * 2 + 1]);

    // ---- Write P (hi/lo split) into smem over dead Q area (group 0 only) ----
    if (wk == 0) {
        char* phi = smem + ASM_P_HI;
        char* plo = smem + ASM_P_LO;
#pragma unroll
        for (int n8 = 0; n8 < 4; n8++) {
            const int j = wn * 32 + n8 * 8 + fc;
            const int u = j >> 3, b = (j & 7) * 2;
            float p0 = sacc[n8][0] * inv0, p1 = sacc[n8][1] * inv0;
            uint32_t hw, lw;
            split2(p0, p1, hw, lw);
            int off0 = row0 * 128 + ((u ^ (row0 & 7)) << 4) + b;
            *(uint32_t*)(phi + off0) = hw;
            *(uint32_t*)(plo + off0) = lw;
            float p2 = sacc[n8][2] * inv1, p3 = sacc[n8][3] * inv1;
            split2(p2, p3, hw, lw);
            int off1 = row1 * 128 + ((u ^ (row1 & 7)) << 4) + b;
            *(uint32_t*)(phi + off1) = hw;
            *(uint32_t*)(plo + off1) = lw;
        }
    }
    CP_WAIT0();            // drain own V stores before P@V
    __syncthreads();

    // ---- P@V: 16 warps as 4m x 4d, warp tile 16(m) x 64(d) ----
    const int wm2 = wid >> 2;
    const int wd  = wid & 3;
    float oacc[8][4];
#pragma unroll
    for (int i = 0; i < 8; i++)
#pragma unroll
        for (int c = 0; c < 4; c++) oacc[i][c] = 0.0f;

    const uint32_t phb = sbase + ASM_P_HI;
    const uint32_t plb = sbase + ASM_P_LO;
    const uint32_t vhb = sbase + ASM_V_HI;
    const uint32_t vlb = sbase + ASM_V_LO;
    const int arow2 = wm2 * 16 + r8 + (q & 1) * 8;

#pragma unroll
    for (int k16 = 0; k16 < 4; k16++) {
        uint32_t ph[4], pl[4];
        uint32_t aoff = arow2 * 128 + (((k16 * 2 + a_ku) ^ (arow2 & 7)) << 4);
        ldsm4(ph, phb + aoff);
        ldsm4(pl, plb + aoff);
        const int jrow = k16 * 16 + (q & 1) * 8 + r8;
#pragma unroll
        for (int dp = 0; dp < 2; dp++) {
            uint32_t vh0[4], vl0[4], vh1[4], vl1[4];
            const int u0 = wd * 8 + (dp * 2) * 2 + (q >> 1);
            const int u1 = wd * 8 + (dp * 2 + 1) * 2 + (q >> 1);
            uint32_t voff0 = jrow * 512 + ((u0 ^ (jrow & 7)) << 4);
            uint32_t voff1 = jrow * 512 + ((u1 ^ (jrow & 7)) << 4);
            ldsm4t(vh0, vhb + voff0);
            ldsm4t(vl0, vlb + voff0);
            ldsm4t(vh1, vhb + voff1);
            ldsm4t(vl1, vlb + voff1);
            float* o0 = oacc[dp * 4 + 0];
            float* o1 = oacc[dp * 4 + 1];
            float* o2 = oacc[dp * 4 + 2];
            float* o3 = oacc[dp * 4 + 3];
            mma16816(o0, ph, &vh0[0]);  mma16816(o1, ph, &vh0[2]);
            mma16816(o2, ph, &vh1[0]);  mma16816(o3, ph, &vh1[2]);
            mma16816(o0, ph, &vl0[0]);  mma16816(o1, ph, &vl0[2]);
            mma16816(o2, ph, &vl1[0]);  mma16816(o3, ph, &vl1[2]);
            mma16816(o0, pl, &vh0[0]);  mma16816(o1, pl, &vh0[2]);
            mma16816(o2, pl, &vh1[0]);  mma16816(o3, pl, &vh1[2]);
        }
    }

    // ---- Output: bf16 hi/lo 4B stores from fragments ----
    const int prow0 = wm2 * 16 + fr;
    const int prow1 = prow0 + 8;
#pragma unroll
    for (int n8 = 0; n8 < 8; n8++) {
        const int d = wd * 64 + n8 * 8 + fc;
        uint32_t hw, lw;
        split2(oacc[n8][0], oacc[n8][1], hw, lw);
        *(uint32_t*)&Ohi[base + (size_t)prow0 * DD + d] = hw;
        *(uint32_t*)&Olo[base + (size_t)prow0 * DD + d] = lw;
        split2(oacc[n8][2], oacc[n8][3], hw, lw);
        *(uint32_t*)&Ohi[base + (size_t)prow1 * DD + d] = hw;
        *(uint32_t*)&Olo[base + (size_t)prow1 * DD + d] = lw;
    }
}

// ---------------------------------------------------------------------------
extern "C" void kernel_launch(void* const* d_in, const int* in_sizes, int n_in,
                              void* d_out, int out_size) {
    (void)in_sizes; (void)n_in; (void)out_size;
    const float* q  = (const float*)d_in[0];
    const float* k  = (const float*)d_in[1];
    const float* v  = (const float*)d_in[2];
    const float* Wq = (const float*)d_in[3];
    const float* Wk = (const float*)d_in[4];
    const float* Wv = (const float*)d_in[5];
    const float* Wo = (const float*)d_in[6];
    const float* bo = (const float*)d_in[7];
    float* out = (float*)d_out;

    __nv_bfloat16 *qhi, *qlo, *khi, *klo, *vhi, *vlo, *aohi, *aolo, *whi, *wlo;
    cudaGetSymbolAddress((void**)&qhi, g_qhi);
    cudaGetSymbolAddress((void**)&qlo, g_qlo);
    cudaGetSymbolAddress((void**)&khi, g_khi);
    cudaGetSymbolAddress((void**)&klo, g_klo);
    cudaGetSymbolAddress((void**)&vhi, g_vhi);
    cudaGetSymbolAddress((void**)&vlo, g_vlo);
    cudaGetSymbolAddress((void**)&aohi, g_aohi);
    cudaGetSymbolAddress((void**)&aolo, g_aolo);
    cudaGetSymbolAddress((void**)&whi, g_w_hi);
    cudaGetSymbolAddress((void**)&wlo, g_w_lo);

    prep_kernel<<<64 + 1024, 256>>>(Wq, Wk, Wv, Wo, whi, wlo);

    cudaFuncSetAttribute(gemm_qkv, cudaFuncAttributeMaxDynamicSharedMemorySize, GSMEM_TOTAL);
    cudaFuncSetAttribute(gemm_out, cudaFuncAttributeMaxDynamicSharedMemorySize, GSMEM_TOTAL);
    cudaFuncSetAttribute(attn_hmma, cudaFuncAttributeMaxDynamicSharedMemorySize, ATTN_SMEM);

    dim3 gg(M_TOTAL / 128, 2, 3);
    gemm_qkv<<<gg, 256, GSMEM_TOTAL>>>(q, k, v, whi, wlo,
                                       qhi, qlo, khi, klo, vhi, vlo);

    attn_hmma<<<VIEWS, 512, ATTN_SMEM>>>(qhi, qlo, khi, klo, vhi, vlo, aohi, aolo);

    dim3 go(M_TOTAL / 128, 2);
    gemm_out<<<go, 256, GSMEM_TOTAL>>>(aohi, aolo, whi + 3 * DD * DD, wlo + 3 * DD * DD,
                                       out, bo, q);
}